// round 14
// baseline (speedup 1.0000x reference)
#include <cuda_runtime.h>
#include <cuda_fp16.h>
#include <cstdint>

// ---------------- problem constants ----------------
static constexpr int B_   = 2;
static constexpr int S_   = 2048;
static constexpr int D_   = 1024;
static constexpr int H_   = 16;
static constexpr int HD_  = 64;
static constexpr int M_   = B_ * S_;    // 4096
static constexpr int BH_  = B_ * H_;    // 32
static constexpr int QT_  = 128;
static constexpr int NQT2_ = S_ / QT_;  // 16
static constexpr float INV_SCALE = 0.125f;  // 1/sqrt(64), exact power of 2

// ---------------- device scratch (fp16) ----------------
__device__ __align__(256) __half g_xq[(size_t)M_ * D_];
__device__ __align__(256) __half g_xk[(size_t)M_ * D_];
__device__ __align__(256) __half g_xv[(size_t)M_ * D_];
__device__ __align__(256) __half g_wq[(size_t)D_ * D_];   // pre-scaled x1/8
__device__ __align__(256) __half g_wk[(size_t)D_ * D_];
__device__ __align__(256) __half g_wv[(size_t)D_ * D_];
__device__ __align__(256) __half g_wo[(size_t)D_ * D_];
__device__ __align__(256) float  g_bqs[D_];               // bq x 1/8 (fp32)
__device__ __align__(256) __half g_q [(size_t)BH_ * S_ * HD_];  // [bh][s][hd], pre-scaled
__device__ __align__(256) __half g_k [(size_t)BH_ * S_ * HD_];  // [bh][s][hd]
__device__ __align__(256) __half g_v [(size_t)BH_ * S_ * HD_];  // TRANSPOSED: [bh][hd][s]
__device__ __align__(256) __half g_ao[(size_t)M_ * D_];

// ---------------- helpers ----------------
__device__ __forceinline__ uint32_t smem_u32(const void* p) {
    uint32_t a;
    asm("{ .reg .u64 t; cvta.to.shared.u64 t, %1; cvt.u32.u64 %0, t; }" : "=r"(a) : "l"(p));
    return a;
}
__device__ __forceinline__ void cp_async16(uint32_t saddr, const void* gaddr) {
    asm volatile("cp.async.cg.shared.global [%0], [%1], 16;" :: "r"(saddr), "l"(gaddr));
}
__device__ __forceinline__ uint32_t f2h2(float x, float y) {
    __half2 h = __floats2half2_rn(x, y);
    return *(uint32_t*)&h;
}
__device__ __forceinline__ void mma16(float* c, uint32_t a0, uint32_t a1, uint32_t a2,
                                      uint32_t a3, uint32_t b0, uint32_t b1) {
    asm volatile(
        "mma.sync.aligned.m16n8k16.row.col.f32.f16.f16.f32 "
        "{%0,%1,%2,%3}, {%4,%5,%6,%7}, {%8,%9}, {%0,%1,%2,%3};"
        : "+f"(c[0]), "+f"(c[1]), "+f"(c[2]), "+f"(c[3])
        : "r"(a0), "r"(a1), "r"(a2), "r"(a3), "r"(b0), "r"(b1));
}
__device__ __forceinline__ void ldsm4(uint32_t addr, uint32_t& r0, uint32_t& r1,
                                      uint32_t& r2, uint32_t& r3) {
    asm volatile("ldmatrix.sync.aligned.m8n8.x4.shared.b16 {%0,%1,%2,%3}, [%4];"
                 : "=r"(r0), "=r"(r1), "=r"(r2), "=r"(r3) : "r"(addr));
}
__device__ __forceinline__ uint32_t lm_addr(uint32_t smemBase, int lane,
                                            int rowBase, int colBase, int strideH) {
    int lr  = lane & 7;
    int r8  = (lane >> 3) & 1;
    int c8  = lane >> 4;
    return smemBase + (uint32_t)((rowBase + lr + r8 * 8) * strideH
                                 + colBase + c8 * 8) * 2u;
}

// ============================================================
// Pre-conversion: fp32 -> fp16. Wq,bq scaled by 1/8 (exact).
// ============================================================
__global__ __launch_bounds__(256) void convert_kernel(
    const float4* __restrict__ q, const float4* __restrict__ k,
    const float4* __restrict__ v, const float4* __restrict__ wq,
    const float4* __restrict__ wk, const float4* __restrict__ wv,
    const float4* __restrict__ wo, const float4* __restrict__ bq)
{
    constexpr int NQ4 = M_ * D_ / 4;
    constexpr int NW4 = D_ * D_ / 4;
    constexpr int NB4 = D_ / 4;
    constexpr int TOT = 3 * NQ4 + 4 * NW4 + NB4;

    for (int i = blockIdx.x * blockDim.x + threadIdx.x; i < TOT;
         i += gridDim.x * blockDim.x) {
        int j = i;
        const float4* src; __half* dsth = nullptr; float sc = 1.f;
        if (j < NQ4)                    { src = q;  dsth = g_xq; }
        else if ((j -= NQ4) < NQ4)      { src = k;  dsth = g_xk; }
        else if ((j -= NQ4) < NQ4)      { src = v;  dsth = g_xv; }
        else if ((j -= NQ4) < NW4)      { src = wq; dsth = g_wq; sc = INV_SCALE; }
        else if ((j -= NW4) < NW4)      { src = wk; dsth = g_wk; }
        else if ((j -= NW4) < NW4)      { src = wv; dsth = g_wv; }
        else if ((j -= NW4) < NW4)      { src = wo; dsth = g_wo; }
        else {
            j -= NW4;
            float4 s = bq[j];
            ((float4*)g_bqs)[j] = make_float4(s.x * INV_SCALE, s.y * INV_SCALE,
                                              s.z * INV_SCALE, s.w * INV_SCALE);
            continue;
        }
        float4 s = src[j];
        uint2 o = make_uint2(f2h2(s.x * sc, s.y * sc), f2h2(s.z * sc, s.w * sc));
        ((uint2*)dsth)[j] = o;
    }
}

// ============================================================
// fp16 mma GEMM: CTA tile 128(M) x 64(N), 8 warps (4m x 2n),
// warp tile 32x32. BK=32, 4-buffer single-sync pipeline.
// 3 CTAs/SM (regs ~80, smem 60KB).
// ============================================================
static constexpr int SAH = 40;                            // halfs/row (80B: LDSM conflict-free)
static constexpr int GEMM_SMEM = 4 * 192 * SAH * 2;       // 61440 B (A 128 rows + B 64 rows)

__global__ __launch_bounds__(256, 3) void gemm_tc_kernel(
    const float* __restrict__ biasK, const float* __restrict__ biasV,
    const float* __restrict__ biasO, float* __restrict__ outPlain, int modeParam)
{
    extern __shared__ __half smh[];

    const int mode = (modeParam == 99) ? (int)blockIdx.z + 1 : modeParam;
    const __half* A = (mode == 1) ? g_xq : (mode == 2) ? g_xk
                    : (mode == 3) ? g_xv : g_ao;
    const __half* W = (mode == 1) ? g_wq : (mode == 2) ? g_wk
                    : (mode == 3) ? g_wv : g_wo;
    const float* bias = (mode == 1) ? g_bqs : (mode == 2) ? biasK
                      : (mode == 3) ? biasV : biasO;

    const int tid  = threadIdx.x;
    const int lane = tid & 31;
    const int w    = tid >> 5;
    const int gg   = lane >> 2;
    const int t4   = lane & 3;
    const int wm   = w & 3;    // 4 m-slices of 32 rows
    const int wn   = w >> 2;   // 2 n-slices of 32 cols
    const int rowBase = blockIdx.y * 128;
    const int colBase = blockIdx.x * 64;
    const int K = D_;

    const uint32_t sBase = smem_u32(smh);

    // buffer b: A (128 rows) at b*192*SAH, B (64 rows) at +128*SAH
    auto stage = [&](int st, int k0) {
        // A: 512 16B-units
#pragma unroll
        for (int ii = 0; ii < 2; ii++) {
            int idx = tid + ii * 256;
            int row = idx >> 2, ch = (idx & 3) * 8;
            uint32_t off = (uint32_t)(st * 192 * SAH + row * SAH + ch) * 2u;
            cp_async16(sBase + off, &A[(size_t)(rowBase + row) * K + k0 + ch]);
        }
        // B: 256 16B-units
        {
            int row = tid >> 2, ch = (tid & 3) * 8;
            uint32_t off = (uint32_t)(st * 192 * SAH + (128 + row) * SAH + ch) * 2u;
            cp_async16(sBase + off, &W[(size_t)(colBase + row) * K + k0 + ch]);
        }
        asm volatile("cp.async.commit_group;" ::: "memory");
    };

    float c[2][4][4];
#pragma unroll
    for (int i = 0; i < 2; i++)
#pragma unroll
        for (int j = 0; j < 4; j++)
#pragma unroll
            for (int q = 0; q < 4; q++) c[i][j][q] = 0.f;

    const int NCH = K / 32;  // 32 chunks
    stage(0, 0);
    stage(1, 32);
    stage(2, 64);

    for (int ch = 0; ch < NCH; ch++) {
        const int rem = NCH - 1 - ch;
        if (rem >= 2)      asm volatile("cp.async.wait_group 2;" ::: "memory");
        else if (rem == 1) asm volatile("cp.async.wait_group 1;" ::: "memory");
        else               asm volatile("cp.async.wait_group 0;" ::: "memory");
        __syncthreads();
        if (ch + 3 < NCH) stage((ch + 3) % 4, (ch + 3) * 32);  // buf consumed at iter ch-1

        const uint32_t aB = sBase + (uint32_t)((ch % 4) * 192 * SAH) * 2u;
        const uint32_t bB = aB + 128 * SAH * 2;
#pragma unroll
        for (int kk = 0; kk < 32; kk += 16) {
            uint32_t af[2][4], bf[4][2];
#pragma unroll
            for (int i = 0; i < 2; i++)
                ldsm4(lm_addr(aB, lane, wm * 32 + i * 16, kk, SAH),
                      af[i][0], af[i][1], af[i][2], af[i][3]);
#pragma unroll
            for (int jp = 0; jp < 2; jp++)
                ldsm4(lm_addr(bB, lane, wn * 32 + jp * 16, kk, SAH),
                      bf[jp * 2][0], bf[jp * 2 + 1][0], bf[jp * 2][1], bf[jp * 2 + 1][1]);
#pragma unroll
            for (int i = 0; i < 2; i++)
#pragma unroll
                for (int j = 0; j < 4; j++)
                    mma16(c[i][j], af[i][0], af[i][1], af[i][2], af[i][3],
                          bf[j][0], bf[j][1]);
        }
    }

#pragma unroll
    for (int i = 0; i < 2; i++) {
#pragma unroll
        for (int j = 0; j < 4; j++) {
            int r0  = rowBase + wm * 32 + i * 16 + gg;
            int col = colBase + wn * 32 + j * 8 + 2 * t4;
            float2 b2 = *(const float2*)&bias[col];
#pragma unroll
            for (int h = 0; h < 2; h++) {
                int m = r0 + h * 8;
                float x = c[i][j][h * 2 + 0] + b2.x;
                float y = c[i][j][h * 2 + 1] + b2.y;
                if (mode == 0) {
                    *(float2*)&outPlain[(size_t)m * D_ + col] = make_float2(x, y);
                } else {
                    int bb = m >> 11, ss = m & (S_ - 1);
                    int hh = col >> 6, hd = col & 63;
                    if (mode == 3) {
                        __half* gv = g_v + (size_t)(bb * H_ + hh) * HD_ * S_;
                        gv[(size_t)hd * S_ + ss]       = __float2half_rn(x);
                        gv[(size_t)(hd + 1) * S_ + ss] = __float2half_rn(y);
                    } else {
                        __half* tgt = (mode == 1) ? g_q : g_k;
                        *(uint32_t*)&tgt[(((size_t)(bb * H_ + hh)) * S_ + ss) * HD_ + hd] =
                            f2h2(x, y);
                    }
                }
            }
        }
    }
}

// ============================================================
// Fused causal attention (fp16 MMA + ldmatrix), two sweeps,
// ONE q-tile per CTA (big-first), triple-buffered K / K+V.
// ============================================================
static constexpr int SQ_  = 68;   // E32 float stride
static constexpr int SH_  = 72;   // half-row stride (144B: LDSM conflict-free)
static constexpr int OFF_EH  = 128 * SQ_ * 4;            // 34816
static constexpr int OFF_K   = OFF_EH + 128 * SH_ * 2;   // 53248
static constexpr int OFF_V   = OFF_K + 3 * 64 * SH_ * 2; // 80896
static constexpr int OFF_INV = OFF_V + 3 * 64 * SH_ * 2; // 108544
static constexpr int ATTN_SMEM = OFF_INV + 128 * 4;      // 109056 B

__global__ __launch_bounds__(256, 2) void attn_kernel(float* __restrict__ P, int writeP)
{
    extern __shared__ char smc[];
    float*  E32   = (float*)smc;
    __half* Qh    = (__half*)smc;            // aliases E32 during Q staging
    __half* Eh    = (__half*)(smc + OFF_EH);
    __half* Kdb   = (__half*)(smc + OFF_K);
    __half* Vdb   = (__half*)(smc + OFF_V);
    float*  inv_s = (float*)(smc + OFF_INV);
    float*  rsc   = (float*)Vdb;             // rowsum scratch (between sweeps only)

    const int tid  = threadIdx.x;
    const int lane = tid & 31;
    const int w    = tid >> 5;
    const int gg   = lane >> 2;
    const int t4   = lane & 3;
    const int wm   = w & 3;
    const int wn   = w >> 2;
    const int bh   = blockIdx.y;
    const int qt   = (NQT2_ - 1) - (int)blockIdx.x;   // big tiles first
    const int q0   = qt * QT_;

    const __half* Qg = g_q + (size_t)bh * S_ * HD_;
    const __half* Kg = g_k + (size_t)bh * S_ * HD_;
    const __half* Vg = g_v + (size_t)bh * S_ * HD_;   // [hd][s]

    const uint32_t sQ = smem_u32(Qh);
    const uint32_t sE = smem_u32(Eh);
    const uint32_t sK = smem_u32(Kdb);
    const uint32_t sV = smem_u32(Vdb);

    auto stageK = [&](int b, int k0) {
#pragma unroll
        for (int i = 0; i < 2; i++) {
            int idx = tid + i * 256;
            int row = idx >> 3, c = (idx & 7) * 8;
            cp_async16(sK + (uint32_t)(b * 64 * SH_ + row * SH_ + c) * 2u,
                       &Kg[(size_t)(k0 + row) * HD_ + c]);
        }
    };
    auto stageV = [&](int b, int k0) {
#pragma unroll
        for (int i = 0; i < 2; i++) {
            int idx = tid + i * 256;
            int row = idx >> 3, c = (idx & 7) * 8;
            cp_async16(sV + (uint32_t)(b * 64 * SH_ + row * SH_ + c) * 2u,
                       &Vg[(size_t)row * S_ + k0 + c]);
        }
    };

    // stage Q tile (fp16, pre-scaled)
#pragma unroll
    for (int i = 0; i < 4; i++) {
        int idx = tid + i * 256;
        int row = idx >> 3, c = (idx & 7) * 8;
        cp_async16(sQ + (uint32_t)(row * SH_ + c) * 2u,
                   &Qg[(size_t)(q0 + row) * HD_ + c]);
    }
    asm volatile("cp.async.commit_group;" ::: "memory");
    asm volatile("cp.async.wait_group 0;" ::: "memory");
    __syncthreads();

    // Q fragments -> registers via ldmatrix
    uint32_t qf[4][8];
#pragma unroll
    for (int ck = 0; ck < 4; ck++)
#pragma unroll
        for (int i = 0; i < 2; i++)
            ldsm4(lm_addr(sQ, lane, wm * 32 + i * 16, ck * 16, SH_),
                  qf[ck][i * 4 + 0], qf[ck][i * 4 + 1],
                  qf[ck][i * 4 + 2], qf[ck][i * 4 + 3]);
    __syncthreads();  // Q region now free (E32 aliases it)

    const int nkt = 2 * qt + 2;

    // ================= sweep 1: rowsums (3-buffer K, 1 sync/iter) ====
    stageK(0, 0);
    asm volatile("cp.async.commit_group;" ::: "memory");
    stageK(1, 64);
    asm volatile("cp.async.commit_group;" ::: "memory");

    float rs[2][2] = {{0.f, 0.f}, {0.f, 0.f}};
    for (int kt = 0; kt < nkt; kt++) {
        if (kt + 1 < nkt) asm volatile("cp.async.wait_group 1;" ::: "memory");
        else              asm volatile("cp.async.wait_group 0;" ::: "memory");
        __syncthreads();  // K(kt) visible + all warps done with buf (kt-1)%3
        if (kt + 2 < nkt) {
            stageK((kt + 2) % 3, (kt + 2) * 64);  // buf consumed at iter kt-1
            asm volatile("cp.async.commit_group;" ::: "memory");
        }

        const uint32_t kB = sK + (uint32_t)((kt % 3) * 64 * SH_) * 2u;
        float s[2][4][4];
#pragma unroll
        for (int i = 0; i < 2; i++)
#pragma unroll
            for (int j = 0; j < 4; j++)
#pragma unroll
                for (int q = 0; q < 4; q++) s[i][j][q] = 0.f;
#pragma unroll
        for (int ck = 0; ck < 4; ck++) {
            uint32_t bf[4][2];
#pragma unroll
            for (int jp = 0; jp < 2; jp++)
                ldsm4(lm_addr(kB, lane, wn * 32 + jp * 16, ck * 16, SH_),
                      bf[jp * 2][0], bf[jp * 2 + 1][0],
                      bf[jp * 2][1], bf[jp * 2 + 1][1]);
#pragma unroll
            for (int i = 0; i < 2; i++)
#pragma unroll
                for (int j = 0; j < 4; j++)
                    mma16(s[i][j], qf[ck][i * 4 + 0], qf[ck][i * 4 + 1],
                          qf[ck][i * 4 + 2], qf[ck][i * 4 + 3], bf[j][0], bf[j][1]);
        }

        const int k0 = kt * 64;
        if (k0 + 63 <= q0 + wm * 32) {
#pragma unroll
            for (int i = 0; i < 2; i++)
#pragma unroll
                for (int j = 0; j < 4; j++) {
                    rs[i][0] += __expf(s[i][j][0]) + __expf(s[i][j][1]);
                    rs[i][1] += __expf(s[i][j][2]) + __expf(s[i][j][3]);
                }
        } else {
#pragma unroll
            for (int i = 0; i < 2; i++) {
                int qiA = q0 + wm * 32 + i * 16 + gg, qiB = qiA + 8;
#pragma unroll
                for (int j = 0; j < 4; j++) {
                    int ki0 = k0 + wn * 32 + j * 8 + 2 * t4, ki1 = ki0 + 1;
                    rs[i][0] += ((ki0 <= qiA) ? __expf(s[i][j][0]) : 0.f)
                              + ((ki1 <= qiA) ? __expf(s[i][j][1]) : 0.f);
                    rs[i][1] += ((ki0 <= qiB) ? __expf(s[i][j][2]) : 0.f)
                              + ((ki1 <= qiB) ? __expf(s[i][j][3]) : 0.f);
                }
            }
        }
    }
#pragma unroll
    for (int i = 0; i < 2; i++) {
#pragma unroll
        for (int h = 0; h < 2; h++) {
            rs[i][h] += __shfl_xor_sync(0xFFFFFFFF, rs[i][h], 1);
            rs[i][h] += __shfl_xor_sync(0xFFFFFFFF, rs[i][h], 2);
        }
    }
    __syncthreads();
    if (t4 == 0) {
#pragma unroll
        for (int i = 0; i < 2; i++) {
            int r0 = wm * 32 + i * 16 + gg;
            rsc[wn * 128 + r0]     = rs[i][0];
            rsc[wn * 128 + r0 + 8] = rs[i][1];
        }
    }
    __syncthreads();
    if (tid < 128) inv_s[tid] = 1.f / (rsc[tid] + rsc[128 + tid]);
    __syncthreads();  // rsc reads done before V restaging below

    // ================= sweep 2: P + O (3-buffer K+V) =================
    float o[2][4][4];
#pragma unroll
    for (int i = 0; i < 2; i++)
#pragma unroll
        for (int j = 0; j < 4; j++)
#pragma unroll
            for (int q = 0; q < 4; q++) o[i][j][q] = 0.f;

    stageK(0, 0); stageV(0, 0);
    asm volatile("cp.async.commit_group;" ::: "memory");
    stageK(1, 64); stageV(1, 64);
    asm volatile("cp.async.commit_group;" ::: "memory");

    for (int kt = 0; kt < S_ / 64; kt++) {
        const int k0 = kt * 64;
        if (kt < nkt) {
            if (kt + 1 < nkt) asm volatile("cp.async.wait_group 1;" ::: "memory");
            else              asm volatile("cp.async.wait_group 0;" ::: "memory");
            __syncthreads();  // K/V(kt) visible + iter kt-1 fully consumed
            if (kt + 2 < nkt) {
                stageK((kt + 2) % 3, (kt + 2) * 64);
                stageV((kt + 2) % 3, (kt + 2) * 64);
                asm volatile("cp.async.commit_group;" ::: "memory");
            }

            const uint32_t kB = sK + (uint32_t)((kt % 3) * 64 * SH_) * 2u;
            const uint32_t vB = sV + (uint32_t)((kt % 3) * 64 * SH_) * 2u;

            float s[2][4][4];
#pragma unroll
            for (int i = 0; i < 2; i++)
#pragma unroll
                for (int j = 0; j < 4; j++)
#pragma unroll
                    for (int q = 0; q < 4; q++) s[i][j][q] = 0.f;
#pragma unroll
            for (int ck = 0; ck < 4; ck++) {
                uint32_t bf[4][2];
#pragma unroll
                for (int jp = 0; jp < 2; jp++)
                    ldsm4(lm_addr(kB, lane, wn * 32 + jp * 16, ck * 16, SH_),
                          bf[jp * 2][0], bf[jp * 2 + 1][0],
                          bf[jp * 2][1], bf[jp * 2 + 1][1]);
#pragma unroll
                for (int i = 0; i < 2; i++)
#pragma unroll
                    for (int j = 0; j < 4; j++)
                        mma16(s[i][j], qf[ck][i * 4 + 0], qf[ck][i * 4 + 1],
                              qf[ck][i * 4 + 2], qf[ck][i * 4 + 3],
                              bf[j][0], bf[j][1]);
            }

            // e_norm = exp * inv, masked only on edge tiles
#pragma unroll
            for (int i = 0; i < 2; i++) {
                int r0 = wm * 32 + i * 16 + gg;
                float invA = inv_s[r0], invB = inv_s[r0 + 8];
                if (k0 + 63 <= q0 + wm * 32) {
#pragma unroll
                    for (int j = 0; j < 4; j++) {
                        s[i][j][0] = __expf(s[i][j][0]) * invA;
                        s[i][j][1] = __expf(s[i][j][1]) * invA;
                        s[i][j][2] = __expf(s[i][j][2]) * invB;
                        s[i][j][3] = __expf(s[i][j][3]) * invB;
                    }
                } else {
                    int qiA = q0 + r0, qiB = qiA + 8;
#pragma unroll
                    for (int j = 0; j < 4; j++) {
                        int ki0 = k0 + wn * 32 + j * 8 + 2 * t4, ki1 = ki0 + 1;
                        s[i][j][0] = (ki0 <= qiA) ? __expf(s[i][j][0]) * invA : 0.f;
                        s[i][j][1] = (ki1 <= qiA) ? __expf(s[i][j][1]) * invA : 0.f;
                        s[i][j][2] = (ki0 <= qiB) ? __expf(s[i][j][2]) * invB : 0.f;
                        s[i][j][3] = (ki1 <= qiB) ? __expf(s[i][j][3]) * invB : 0.f;
                    }
                }
            }

            // dual-store E: fp16 for MMA, fp32 for coalesced P write
#pragma unroll
            for (int i = 0; i < 2; i++) {
                int r0 = wm * 32 + i * 16 + gg;
#pragma unroll
                for (int j = 0; j < 4; j++) {
                    int cl = wn * 32 + j * 8 + 2 * t4;
                    *(uint32_t*)&Eh[r0 * SH_ + cl]       = f2h2(s[i][j][0], s[i][j][1]);
                    *(uint32_t*)&Eh[(r0 + 8) * SH_ + cl] = f2h2(s[i][j][2], s[i][j][3]);
                    if (writeP) {
                        *(float2*)&E32[r0 * SQ_ + cl] =
                            make_float2(s[i][j][0], s[i][j][1]);
                        *(float2*)&E32[(r0 + 8) * SQ_ + cl] =
                            make_float2(s[i][j][2], s[i][j][3]);
                    }
                }
            }
            __syncthreads();  // E complete

            if (writeP) {
                float* Pd = P + (size_t)bh * S_ * S_ + (size_t)q0 * S_ + k0;
#pragma unroll
                for (int i = 0; i < 8; i++) {
                    int idx = tid + i * 256;
                    int row = idx >> 4, cc = (idx & 15) * 4;
                    *(float4*)&Pd[(size_t)row * S_ + cc] =
                        *(const float4*)&E32[row * SQ_ + cc];
                }
            }

            // O += E_norm @ V
#pragma unroll
            for (int ck = 0; ck < 4; ck++) {
                uint32_t af[2][4], bf[4][2];
#pragma unroll
                for (int i = 0; i < 2; i++)
                    ldsm4(lm_addr(sE, lane, wm * 32 + i * 16, ck * 16, SH_),
                          af[i][0], af[i][1], af[i][2], af[i][3]);
#pragma unroll
                for (int jp = 0; jp < 2; jp++)
                    ldsm4(lm_addr(vB, lane, wn * 32 + jp * 16, ck * 16, SH_),
                          bf[jp * 2][0], bf[jp * 2 + 1][0],
                          bf[jp * 2][1], bf[jp * 2 + 1][1]);
#pragma unroll
                for (int i = 0; i < 2; i++)
#pragma unroll
                    for (int j = 0; j < 4; j++)
                        mma16(o[i][j], af[i][0], af[i][1], af[i][2], af[i][3],
                              bf[j][0], bf[j][1]);
            }
        } else if (writeP) {
            float* Pd = P + (size_t)bh * S_ * S_ + (size_t)q0 * S_ + k0;
            const float4 z = make_float4(0.f, 0.f, 0.f, 0.f);
#pragma unroll
            for (int i = 0; i < 8; i++) {
                int idx = tid + i * 256;
                int row = idx >> 4, cc = (idx & 15) * 4;
                *(float4*)&Pd[(size_t)row * S_ + cc] = z;
            }
        }
    }

    // epilogue: O -> g_ao (fp16)
    const int bb = bh >> 4, hh = bh & 15;
#pragma unroll
    for (int i = 0; i < 2; i++) {
        int r0 = wm * 32 + i * 16 + gg;
        int mA = bb * S_ + q0 + r0;
#pragma unroll
        for (int j = 0; j < 4; j++) {
            int cl = hh * 64 + wn * 32 + j * 8 + 2 * t4;
            *(uint32_t*)&g_ao[(size_t)mA * D_ + cl]       = f2h2(o[i][j][0], o[i][j][1]);
            *(uint32_t*)&g_ao[(size_t)(mA + 8) * D_ + cl] = f2h2(o[i][j][2], o[i][j][3]);
        }
    }
}

// ============================================================
extern "C" void kernel_launch(void* const* d_in, const int* in_sizes, int n_in,
                              void* d_out, int out_size)
{
    const float* query = (const float*)d_in[0];
    const float* key_  = (const float*)d_in[1];
    const float* value = (const float*)d_in[2];
    // d_in[3] = causal mask — handled analytically
    const float* Wq = (const float*)d_in[4];
    const float* bq = (const float*)d_in[5];
    const float* Wk = (const float*)d_in[6];
    const float* bk = (const float*)d_in[7];
    const float* Wv = (const float*)d_in[8];
    const float* bv = (const float*)d_in[9];
    const float* Wo = (const float*)d_in[10];
    const float* bo = (const float*)d_in[11];
    float* out = (float*)d_out;

    const long long outN  = (long long)M_ * D_;
    const long long attnN = (long long)BH_ * S_ * S_;

    int hasOut = 1, hasAttn = 0;
    float* Pdst = nullptr;
    if ((long long)out_size >= outN + attnN) { hasAttn = 1; Pdst = out + outN; }
    else if ((long long)out_size == attnN)   { hasOut = 0; hasAttn = 1; Pdst = out; }

    cudaFuncSetAttribute(attn_kernel,
                         cudaFuncAttributeMaxDynamicSharedMemorySize, ATTN_SMEM);
    cudaFuncSetAttribute(gemm_tc_kernel,
                         cudaFuncAttributeMaxDynamicSharedMemorySize, GEMM_SMEM);

    convert_kernel<<<512, 256>>>(
        (const float4*)query, (const float4*)key_, (const float4*)value,
        (const float4*)Wq, (const float4*)Wk, (const float4*)Wv,
        (const float4*)Wo, (const float4*)bq);

    // fused Q/K/V projections: 16 x 32 x 3 = 1536 CTAs
    gemm_tc_kernel<<<dim3(D_ / 64, M_ / 128, 3), 256, GEMM_SMEM>>>(
        bk, bv, nullptr, nullptr, 99);

    // attention: one q-tile per CTA, big-first
    attn_kernel<<<dim3(NQT2_, BH_), 256, ATTN_SMEM>>>(Pdst, hasAttn);

    if (hasOut)
        gemm_tc_kernel<<<dim3(D_ / 64, M_ / 128, 1), 256, GEMM_SMEM>>>(
            nullptr, nullptr, bo, out, 0);
}

// round 15
// speedup vs baseline: 1.1105x; 1.1105x over previous
#include <cuda_runtime.h>
#include <cuda_fp16.h>
#include <cstdint>

// ---------------- problem constants ----------------
static constexpr int B_   = 2;
static constexpr int S_   = 2048;
static constexpr int D_   = 1024;
static constexpr int H_   = 16;
static constexpr int HD_  = 64;
static constexpr int M_   = B_ * S_;    // 4096
static constexpr int BH_  = B_ * H_;    // 32
static constexpr int QT_  = 128;
static constexpr int NQT2_ = S_ / QT_;  // 16
static constexpr float INV_SCALE = 0.125f;  // 1/sqrt(64), exact power of 2

// ---------------- device scratch (fp16) ----------------
__device__ __align__(256) __half g_xq[(size_t)M_ * D_];
__device__ __align__(256) __half g_xk[(size_t)M_ * D_];
__device__ __align__(256) __half g_xv[(size_t)M_ * D_];
__device__ __align__(256) __half g_wq[(size_t)D_ * D_];   // pre-scaled x1/8
__device__ __align__(256) __half g_wk[(size_t)D_ * D_];
__device__ __align__(256) __half g_wv[(size_t)D_ * D_];
__device__ __align__(256) __half g_wo[(size_t)D_ * D_];
__device__ __align__(256) float  g_bqs[D_];               // bq x 1/8 (fp32)
__device__ __align__(256) __half g_q [(size_t)BH_ * S_ * HD_];  // [bh][s][hd], pre-scaled
__device__ __align__(256) __half g_k [(size_t)BH_ * S_ * HD_];  // [bh][s][hd]
__device__ __align__(256) __half g_v [(size_t)BH_ * S_ * HD_];  // TRANSPOSED: [bh][hd][s]
__device__ __align__(256) __half g_ao[(size_t)M_ * D_];

// ---------------- helpers ----------------
__device__ __forceinline__ uint32_t smem_u32(const void* p) {
    uint32_t a;
    asm("{ .reg .u64 t; cvta.to.shared.u64 t, %1; cvt.u32.u64 %0, t; }" : "=r"(a) : "l"(p));
    return a;
}
__device__ __forceinline__ void cp_async16(uint32_t saddr, const void* gaddr) {
    asm volatile("cp.async.cg.shared.global [%0], [%1], 16;" :: "r"(saddr), "l"(gaddr));
}
__device__ __forceinline__ uint32_t f2h2(float x, float y) {
    __half2 h = __floats2half2_rn(x, y);
    return *(uint32_t*)&h;
}
__device__ __forceinline__ void mma16(float* c, uint32_t a0, uint32_t a1, uint32_t a2,
                                      uint32_t a3, uint32_t b0, uint32_t b1) {
    asm volatile(
        "mma.sync.aligned.m16n8k16.row.col.f32.f16.f16.f32 "
        "{%0,%1,%2,%3}, {%4,%5,%6,%7}, {%8,%9}, {%0,%1,%2,%3};"
        : "+f"(c[0]), "+f"(c[1]), "+f"(c[2]), "+f"(c[3])
        : "r"(a0), "r"(a1), "r"(a2), "r"(a3), "r"(b0), "r"(b1));
}
__device__ __forceinline__ void ldsm4(uint32_t addr, uint32_t& r0, uint32_t& r1,
                                      uint32_t& r2, uint32_t& r3) {
    asm volatile("ldmatrix.sync.aligned.m8n8.x4.shared.b16 {%0,%1,%2,%3}, [%4];"
                 : "=r"(r0), "=r"(r1), "=r"(r2), "=r"(r3) : "r"(addr));
}
__device__ __forceinline__ uint32_t lm_addr(uint32_t smemBase, int lane,
                                            int rowBase, int colBase, int strideH) {
    int lr  = lane & 7;
    int r8  = (lane >> 3) & 1;
    int c8  = lane >> 4;
    return smemBase + (uint32_t)((rowBase + lr + r8 * 8) * strideH
                                 + colBase + c8 * 8) * 2u;
}

// ============================================================
// Pre-conversion: fp32 -> fp16. Wq,bq scaled by 1/8 (exact).
// ============================================================
__global__ __launch_bounds__(256) void convert_kernel(
    const float4* __restrict__ q, const float4* __restrict__ k,
    const float4* __restrict__ v, const float4* __restrict__ wq,
    const float4* __restrict__ wk, const float4* __restrict__ wv,
    const float4* __restrict__ wo, const float4* __restrict__ bq)
{
    constexpr int NQ4 = M_ * D_ / 4;
    constexpr int NW4 = D_ * D_ / 4;
    constexpr int NB4 = D_ / 4;
    constexpr int TOT = 3 * NQ4 + 4 * NW4 + NB4;

    for (int i = blockIdx.x * blockDim.x + threadIdx.x; i < TOT;
         i += gridDim.x * blockDim.x) {
        int j = i;
        const float4* src; __half* dsth = nullptr; float sc = 1.f;
        if (j < NQ4)                    { src = q;  dsth = g_xq; }
        else if ((j -= NQ4) < NQ4)      { src = k;  dsth = g_xk; }
        else if ((j -= NQ4) < NQ4)      { src = v;  dsth = g_xv; }
        else if ((j -= NQ4) < NW4)      { src = wq; dsth = g_wq; sc = INV_SCALE; }
        else if ((j -= NW4) < NW4)      { src = wk; dsth = g_wk; }
        else if ((j -= NW4) < NW4)      { src = wv; dsth = g_wv; }
        else if ((j -= NW4) < NW4)      { src = wo; dsth = g_wo; }
        else {
            j -= NW4;
            float4 s = bq[j];
            ((float4*)g_bqs)[j] = make_float4(s.x * INV_SCALE, s.y * INV_SCALE,
                                              s.z * INV_SCALE, s.w * INV_SCALE);
            continue;
        }
        float4 s = src[j];
        uint2 o = make_uint2(f2h2(s.x * sc, s.y * sc), f2h2(s.z * sc, s.w * sc));
        ((uint2*)dsth)[j] = o;
    }
}

// ============================================================
// fp16 mma GEMM: CTA tile 128(M) x 64(N), 8 warps (4m x 2n),
// warp tile 32x32. BK=32, 4-buffer single-sync pipeline. 3 CTAs/SM.
// ============================================================
static constexpr int SAH = 40;                            // halfs/row (80B: LDSM conflict-free)
static constexpr int GEMM_SMEM = 4 * 192 * SAH * 2;       // 61440 B

__global__ __launch_bounds__(256, 3) void gemm_tc_kernel(
    const float* __restrict__ biasK, const float* __restrict__ biasV,
    const float* __restrict__ biasO, float* __restrict__ outPlain, int modeParam)
{
    extern __shared__ __half smh[];

    const int mode = (modeParam == 99) ? (int)blockIdx.z + 1 : modeParam;
    const __half* A = (mode == 1) ? g_xq : (mode == 2) ? g_xk
                    : (mode == 3) ? g_xv : g_ao;
    const __half* W = (mode == 1) ? g_wq : (mode == 2) ? g_wk
                    : (mode == 3) ? g_wv : g_wo;
    const float* bias = (mode == 1) ? g_bqs : (mode == 2) ? biasK
                      : (mode == 3) ? biasV : biasO;

    const int tid  = threadIdx.x;
    const int lane = tid & 31;
    const int w    = tid >> 5;
    const int gg   = lane >> 2;
    const int t4   = lane & 3;
    const int wm   = w & 3;    // 4 m-slices of 32 rows
    const int wn   = w >> 2;   // 2 n-slices of 32 cols
    const int rowBase = blockIdx.y * 128;
    const int colBase = blockIdx.x * 64;
    const int K = D_;

    const uint32_t sBase = smem_u32(smh);

    // buffer b: A (128 rows) at b*192*SAH, B (64 rows) at +128*SAH
    auto stage = [&](int st, int k0) {
#pragma unroll
        for (int ii = 0; ii < 2; ii++) {
            int idx = tid + ii * 256;
            int row = idx >> 2, ch = (idx & 3) * 8;
            uint32_t off = (uint32_t)(st * 192 * SAH + row * SAH + ch) * 2u;
            cp_async16(sBase + off, &A[(size_t)(rowBase + row) * K + k0 + ch]);
        }
        {
            int row = tid >> 2, ch = (tid & 3) * 8;
            uint32_t off = (uint32_t)(st * 192 * SAH + (128 + row) * SAH + ch) * 2u;
            cp_async16(sBase + off, &W[(size_t)(colBase + row) * K + k0 + ch]);
        }
        asm volatile("cp.async.commit_group;" ::: "memory");
    };

    float c[2][4][4];
#pragma unroll
    for (int i = 0; i < 2; i++)
#pragma unroll
        for (int j = 0; j < 4; j++)
#pragma unroll
            for (int q = 0; q < 4; q++) c[i][j][q] = 0.f;

    const int NCH = K / 32;  // 32 chunks
    stage(0, 0);
    stage(1, 32);
    stage(2, 64);

    for (int ch = 0; ch < NCH; ch++) {
        const int rem = NCH - 1 - ch;
        if (rem >= 2)      asm volatile("cp.async.wait_group 2;" ::: "memory");
        else if (rem == 1) asm volatile("cp.async.wait_group 1;" ::: "memory");
        else               asm volatile("cp.async.wait_group 0;" ::: "memory");
        __syncthreads();
        if (ch + 3 < NCH) stage((ch + 3) % 4, (ch + 3) * 32);

        const uint32_t aB = sBase + (uint32_t)((ch % 4) * 192 * SAH) * 2u;
        const uint32_t bB = aB + 128 * SAH * 2;
#pragma unroll
        for (int kk = 0; kk < 32; kk += 16) {
            uint32_t af[2][4], bf[4][2];
#pragma unroll
            for (int i = 0; i < 2; i++)
                ldsm4(lm_addr(aB, lane, wm * 32 + i * 16, kk, SAH),
                      af[i][0], af[i][1], af[i][2], af[i][3]);
#pragma unroll
            for (int jp = 0; jp < 2; jp++)
                ldsm4(lm_addr(bB, lane, wn * 32 + jp * 16, kk, SAH),
                      bf[jp * 2][0], bf[jp * 2 + 1][0], bf[jp * 2][1], bf[jp * 2 + 1][1]);
#pragma unroll
            for (int i = 0; i < 2; i++)
#pragma unroll
                for (int j = 0; j < 4; j++)
                    mma16(c[i][j], af[i][0], af[i][1], af[i][2], af[i][3],
                          bf[j][0], bf[j][1]);
        }
    }

#pragma unroll
    for (int i = 0; i < 2; i++) {
#pragma unroll
        for (int j = 0; j < 4; j++) {
            int r0  = rowBase + wm * 32 + i * 16 + gg;
            int col = colBase + wn * 32 + j * 8 + 2 * t4;
            float2 b2 = *(const float2*)&bias[col];
#pragma unroll
            for (int h = 0; h < 2; h++) {
                int m = r0 + h * 8;
                float x = c[i][j][h * 2 + 0] + b2.x;
                float y = c[i][j][h * 2 + 1] + b2.y;
                if (mode == 0) {
                    *(float2*)&outPlain[(size_t)m * D_ + col] = make_float2(x, y);
                } else {
                    int bb = m >> 11, ss = m & (S_ - 1);
                    int hh = col >> 6, hd = col & 63;
                    if (mode == 3) {
                        __half* gv = g_v + (size_t)(bb * H_ + hh) * HD_ * S_;
                        gv[(size_t)hd * S_ + ss]       = __float2half_rn(x);
                        gv[(size_t)(hd + 1) * S_ + ss] = __float2half_rn(y);
                    } else {
                        __half* tgt = (mode == 1) ? g_q : g_k;
                        *(uint32_t*)&tgt[(((size_t)(bb * H_ + hh)) * S_ + ss) * HD_ + hd] =
                            f2h2(x, y);
                    }
                }
            }
        }
    }
}

// ============================================================
// Fused causal attention (fp16 MMA + ldmatrix), two sweeps,
// PAIRED q-tiles per CTA (uniform 34 k-tiles, one wave),
// triple-buffered K / K+V, single-sync pipeline. (R13-validated)
// ============================================================
static constexpr int SQ_  = 68;   // E32 float stride
static constexpr int SH_  = 72;   // half-row stride (144B: LDSM conflict-free)
static constexpr int OFF_EH  = 128 * SQ_ * 4;            // 34816
static constexpr int OFF_K   = OFF_EH + 128 * SH_ * 2;   // 53248
static constexpr int OFF_V   = OFF_K + 3 * 64 * SH_ * 2; // 80896
static constexpr int OFF_INV = OFF_V + 3 * 64 * SH_ * 2; // 108544
static constexpr int ATTN_SMEM = OFF_INV + 128 * 4;      // 109056 B

__global__ __launch_bounds__(256, 2) void attn_kernel(float* __restrict__ P, int writeP)
{
    extern __shared__ char smc[];
    float*  E32   = (float*)smc;
    __half* Qh    = (__half*)smc;            // aliases E32 during Q staging
    __half* Eh    = (__half*)(smc + OFF_EH);
    __half* Kdb   = (__half*)(smc + OFF_K);
    __half* Vdb   = (__half*)(smc + OFF_V);
    float*  inv_s = (float*)(smc + OFF_INV);
    float*  rsc   = (float*)Vdb;             // rowsum scratch (between sweeps only)

    const int tid  = threadIdx.x;
    const int lane = tid & 31;
    const int w    = tid >> 5;
    const int gg   = lane >> 2;
    const int t4   = lane & 3;
    const int wm   = w & 3;
    const int wn   = w >> 2;
    const int bh   = blockIdx.y;

    const __half* Qg = g_q + (size_t)bh * S_ * HD_;
    const __half* Kg = g_k + (size_t)bh * S_ * HD_;
    const __half* Vg = g_v + (size_t)bh * S_ * HD_;   // [hd][s]

    const uint32_t sQ = smem_u32(Qh);
    const uint32_t sE = smem_u32(Eh);
    const uint32_t sK = smem_u32(Kdb);
    const uint32_t sV = smem_u32(Vdb);

    auto stageK = [&](int b, int k0) {
#pragma unroll
        for (int i = 0; i < 2; i++) {
            int idx = tid + i * 256;
            int row = idx >> 3, c = (idx & 7) * 8;
            cp_async16(sK + (uint32_t)(b * 64 * SH_ + row * SH_ + c) * 2u,
                       &Kg[(size_t)(k0 + row) * HD_ + c]);
        }
    };
    auto stageV = [&](int b, int k0) {
#pragma unroll
        for (int i = 0; i < 2; i++) {
            int idx = tid + i * 256;
            int row = idx >> 3, c = (idx & 7) * 8;
            cp_async16(sV + (uint32_t)(b * 64 * SH_ + row * SH_ + c) * 2u,
                       &Vg[(size_t)row * S_ + k0 + c]);
        }
    };

#pragma unroll 1
    for (int p = 0; p < 2; p++) {
        const int qt = p == 0 ? (NQT2_ - 1) - (int)blockIdx.x : (int)blockIdx.x;
        const int q0 = qt * QT_;
        __syncthreads();  // previous pair fully done

        // stage Q tile (fp16, pre-scaled)
#pragma unroll
        for (int i = 0; i < 4; i++) {
            int idx = tid + i * 256;
            int row = idx >> 3, c = (idx & 7) * 8;
            cp_async16(sQ + (uint32_t)(row * SH_ + c) * 2u,
                       &Qg[(size_t)(q0 + row) * HD_ + c]);
        }
        asm volatile("cp.async.commit_group;" ::: "memory");
        asm volatile("cp.async.wait_group 0;" ::: "memory");
        __syncthreads();

        // Q fragments -> registers via ldmatrix
        uint32_t qf[4][8];
#pragma unroll
        for (int ck = 0; ck < 4; ck++)
#pragma unroll
            for (int i = 0; i < 2; i++)
                ldsm4(lm_addr(sQ, lane, wm * 32 + i * 16, ck * 16, SH_),
                      qf[ck][i * 4 + 0], qf[ck][i * 4 + 1],
                      qf[ck][i * 4 + 2], qf[ck][i * 4 + 3]);
        __syncthreads();  // Q region now free (E32 aliases it)

        const int nkt = 2 * qt + 2;  // >= 2 always

        // ================= sweep 1: rowsums (3-buffer K, 1 sync/iter) ====
        stageK(0, 0);
        asm volatile("cp.async.commit_group;" ::: "memory");
        stageK(1, 64);
        asm volatile("cp.async.commit_group;" ::: "memory");

        float rs[2][2] = {{0.f, 0.f}, {0.f, 0.f}};
        for (int kt = 0; kt < nkt; kt++) {
            if (kt + 1 < nkt) asm volatile("cp.async.wait_group 1;" ::: "memory");
            else              asm volatile("cp.async.wait_group 0;" ::: "memory");
            __syncthreads();  // K(kt) visible + all warps done with buf (kt-1)%3
            if (kt + 2 < nkt) {
                stageK((kt + 2) % 3, (kt + 2) * 64);
                asm volatile("cp.async.commit_group;" ::: "memory");
            }

            const uint32_t kB = sK + (uint32_t)((kt % 3) * 64 * SH_) * 2u;
            float s[2][4][4];
#pragma unroll
            for (int i = 0; i < 2; i++)
#pragma unroll
                for (int j = 0; j < 4; j++)
#pragma unroll
                    for (int q = 0; q < 4; q++) s[i][j][q] = 0.f;
#pragma unroll
            for (int ck = 0; ck < 4; ck++) {
                uint32_t bf[4][2];
#pragma unroll
                for (int jp = 0; jp < 2; jp++)
                    ldsm4(lm_addr(kB, lane, wn * 32 + jp * 16, ck * 16, SH_),
                          bf[jp * 2][0], bf[jp * 2 + 1][0],
                          bf[jp * 2][1], bf[jp * 2 + 1][1]);
#pragma unroll
                for (int i = 0; i < 2; i++)
#pragma unroll
                    for (int j = 0; j < 4; j++)
                        mma16(s[i][j], qf[ck][i * 4 + 0], qf[ck][i * 4 + 1],
                              qf[ck][i * 4 + 2], qf[ck][i * 4 + 3], bf[j][0], bf[j][1]);
            }

            const int k0 = kt * 64;
            if (k0 + 63 <= q0 + wm * 32) {
#pragma unroll
                for (int i = 0; i < 2; i++)
#pragma unroll
                    for (int j = 0; j < 4; j++) {
                        rs[i][0] += __expf(s[i][j][0]) + __expf(s[i][j][1]);
                        rs[i][1] += __expf(s[i][j][2]) + __expf(s[i][j][3]);
                    }
            } else {
#pragma unroll
                for (int i = 0; i < 2; i++) {
                    int qiA = q0 + wm * 32 + i * 16 + gg, qiB = qiA + 8;
#pragma unroll
                    for (int j = 0; j < 4; j++) {
                        int ki0 = k0 + wn * 32 + j * 8 + 2 * t4, ki1 = ki0 + 1;
                        rs[i][0] += ((ki0 <= qiA) ? __expf(s[i][j][0]) : 0.f)
                                  + ((ki1 <= qiA) ? __expf(s[i][j][1]) : 0.f);
                        rs[i][1] += ((ki0 <= qiB) ? __expf(s[i][j][2]) : 0.f)
                                  + ((ki1 <= qiB) ? __expf(s[i][j][3]) : 0.f);
                    }
                }
            }
        }
#pragma unroll
        for (int i = 0; i < 2; i++) {
#pragma unroll
            for (int h = 0; h < 2; h++) {
                rs[i][h] += __shfl_xor_sync(0xFFFFFFFF, rs[i][h], 1);
                rs[i][h] += __shfl_xor_sync(0xFFFFFFFF, rs[i][h], 2);
            }
        }
        __syncthreads();
        if (t4 == 0) {
#pragma unroll
            for (int i = 0; i < 2; i++) {
                int r0 = wm * 32 + i * 16 + gg;
                rsc[wn * 128 + r0]     = rs[i][0];
                rsc[wn * 128 + r0 + 8] = rs[i][1];
            }
        }
        __syncthreads();
        if (tid < 128) inv_s[tid] = 1.f / (rsc[tid] + rsc[128 + tid]);
        __syncthreads();  // rsc reads done before V restaging below

        // ================= sweep 2: P + O (3-buffer K+V) =================
        float o[2][4][4];
#pragma unroll
        for (int i = 0; i < 2; i++)
#pragma unroll
            for (int j = 0; j < 4; j++)
#pragma unroll
                for (int q = 0; q < 4; q++) o[i][j][q] = 0.f;

        stageK(0, 0); stageV(0, 0);
        asm volatile("cp.async.commit_group;" ::: "memory");
        stageK(1, 64); stageV(1, 64);
        asm volatile("cp.async.commit_group;" ::: "memory");

        for (int kt = 0; kt < S_ / 64; kt++) {
            const int k0 = kt * 64;
            if (kt < nkt) {
                if (kt + 1 < nkt) asm volatile("cp.async.wait_group 1;" ::: "memory");
                else              asm volatile("cp.async.wait_group 0;" ::: "memory");
                __syncthreads();  // K/V(kt) visible + iter kt-1 fully consumed
                if (kt + 2 < nkt) {
                    stageK((kt + 2) % 3, (kt + 2) * 64);
                    stageV((kt + 2) % 3, (kt + 2) * 64);
                    asm volatile("cp.async.commit_group;" ::: "memory");
                }

                const uint32_t kB = sK + (uint32_t)((kt % 3) * 64 * SH_) * 2u;
                const uint32_t vB = sV + (uint32_t)((kt % 3) * 64 * SH_) * 2u;

                float s[2][4][4];
#pragma unroll
                for (int i = 0; i < 2; i++)
#pragma unroll
                    for (int j = 0; j < 4; j++)
#pragma unroll
                        for (int q = 0; q < 4; q++) s[i][j][q] = 0.f;
#pragma unroll
                for (int ck = 0; ck < 4; ck++) {
                    uint32_t bf[4][2];
#pragma unroll
                    for (int jp = 0; jp < 2; jp++)
                        ldsm4(lm_addr(kB, lane, wn * 32 + jp * 16, ck * 16, SH_),
                              bf[jp * 2][0], bf[jp * 2 + 1][0],
                              bf[jp * 2][1], bf[jp * 2 + 1][1]);
#pragma unroll
                    for (int i = 0; i < 2; i++)
#pragma unroll
                        for (int j = 0; j < 4; j++)
                            mma16(s[i][j], qf[ck][i * 4 + 0], qf[ck][i * 4 + 1],
                                  qf[ck][i * 4 + 2], qf[ck][i * 4 + 3],
                                  bf[j][0], bf[j][1]);
                }

                // e_norm = exp * inv, masked only on edge tiles
#pragma unroll
                for (int i = 0; i < 2; i++) {
                    int r0 = wm * 32 + i * 16 + gg;
                    float invA = inv_s[r0], invB = inv_s[r0 + 8];
                    if (k0 + 63 <= q0 + wm * 32) {
#pragma unroll
                        for (int j = 0; j < 4; j++) {
                            s[i][j][0] = __expf(s[i][j][0]) * invA;
                            s[i][j][1] = __expf(s[i][j][1]) * invA;
                            s[i][j][2] = __expf(s[i][j][2]) * invB;
                            s[i][j][3] = __expf(s[i][j][3]) * invB;
                        }
                    } else {
                        int qiA = q0 + r0, qiB = qiA + 8;
#pragma unroll
                        for (int j = 0; j < 4; j++) {
                            int ki0 = k0 + wn * 32 + j * 8 + 2 * t4, ki1 = ki0 + 1;
                            s[i][j][0] = (ki0 <= qiA) ? __expf(s[i][j][0]) * invA : 0.f;
                            s[i][j][1] = (ki1 <= qiA) ? __expf(s[i][j][1]) * invA : 0.f;
                            s[i][j][2] = (ki0 <= qiB) ? __expf(s[i][j][2]) * invB : 0.f;
                            s[i][j][3] = (ki1 <= qiB) ? __expf(s[i][j][3]) * invB : 0.f;
                        }
                    }
                }

                // dual-store E: fp16 for MMA, fp32 for coalesced P write
#pragma unroll
                for (int i = 0; i < 2; i++) {
                    int r0 = wm * 32 + i * 16 + gg;
#pragma unroll
                    for (int j = 0; j < 4; j++) {
                        int cl = wn * 32 + j * 8 + 2 * t4;
                        *(uint32_t*)&Eh[r0 * SH_ + cl]       = f2h2(s[i][j][0], s[i][j][1]);
                        *(uint32_t*)&Eh[(r0 + 8) * SH_ + cl] = f2h2(s[i][j][2], s[i][j][3]);
                        if (writeP) {
                            *(float2*)&E32[r0 * SQ_ + cl] =
                                make_float2(s[i][j][0], s[i][j][1]);
                            *(float2*)&E32[(r0 + 8) * SQ_ + cl] =
                                make_float2(s[i][j][2], s[i][j][3]);
                        }
                    }
                }
                __syncthreads();  // E complete

                if (writeP) {
                    float* Pd = P + (size_t)bh * S_ * S_ + (size_t)q0 * S_ + k0;
#pragma unroll
                    for (int i = 0; i < 8; i++) {
                        int idx = tid + i * 256;
                        int row = idx >> 4, cc = (idx & 15) * 4;
                        *(float4*)&Pd[(size_t)row * S_ + cc] =
                            *(const float4*)&E32[row * SQ_ + cc];
                    }
                }

                // O += E_norm @ V
#pragma unroll
                for (int ck = 0; ck < 4; ck++) {
                    uint32_t af[2][4], bf[4][2];
#pragma unroll
                    for (int i = 0; i < 2; i++)
                        ldsm4(lm_addr(sE, lane, wm * 32 + i * 16, ck * 16, SH_),
                              af[i][0], af[i][1], af[i][2], af[i][3]);
#pragma unroll
                    for (int jp = 0; jp < 2; jp++)
                        ldsm4(lm_addr(vB, lane, wn * 32 + jp * 16, ck * 16, SH_),
                              bf[jp * 2][0], bf[jp * 2 + 1][0],
                              bf[jp * 2][1], bf[jp * 2 + 1][1]);
#pragma unroll
                    for (int i = 0; i < 2; i++)
#pragma unroll
                        for (int j = 0; j < 4; j++)
                            mma16(o[i][j], af[i][0], af[i][1], af[i][2], af[i][3],
                                  bf[j][0], bf[j][1]);
                }
            } else if (writeP) {
                float* Pd = P + (size_t)bh * S_ * S_ + (size_t)q0 * S_ + k0;
                const float4 z = make_float4(0.f, 0.f, 0.f, 0.f);
#pragma unroll
                for (int i = 0; i < 8; i++) {
                    int idx = tid + i * 256;
                    int row = idx >> 4, cc = (idx & 15) * 4;
                    *(float4*)&Pd[(size_t)row * S_ + cc] = z;
                }
            }
        }

        // epilogue: O -> g_ao (fp16)
        const int bb = bh >> 4, hh = bh & 15;
#pragma unroll
        for (int i = 0; i < 2; i++) {
            int r0 = wm * 32 + i * 16 + gg;
            int mA = bb * S_ + q0 + r0;
#pragma unroll
            for (int j = 0; j < 4; j++) {
                int cl = hh * 64 + wn * 32 + j * 8 + 2 * t4;
                *(uint32_t*)&g_ao[(size_t)mA * D_ + cl]       = f2h2(o[i][j][0], o[i][j][1]);
                *(uint32_t*)&g_ao[(size_t)(mA + 8) * D_ + cl] = f2h2(o[i][j][2], o[i][j][3]);
            }
        }
    }
}

// ============================================================
extern "C" void kernel_launch(void* const* d_in, const int* in_sizes, int n_in,
                              void* d_out, int out_size)
{
    const float* query = (const float*)d_in[0];
    const float* key_  = (const float*)d_in[1];
    const float* value = (const float*)d_in[2];
    // d_in[3] = causal mask — handled analytically
    const float* Wq = (const float*)d_in[4];
    const float* bq = (const float*)d_in[5];
    const float* Wk = (const float*)d_in[6];
    const float* bk = (const float*)d_in[7];
    const float* Wv = (const float*)d_in[8];
    const float* bv = (const float*)d_in[9];
    const float* Wo = (const float*)d_in[10];
    const float* bo = (const float*)d_in[11];
    float* out = (float*)d_out;

    const long long outN  = (long long)M_ * D_;
    const long long attnN = (long long)BH_ * S_ * S_;

    int hasOut = 1, hasAttn = 0;
    float* Pdst = nullptr;
    if ((long long)out_size >= outN + attnN) { hasAttn = 1; Pdst = out + outN; }
    else if ((long long)out_size == attnN)   { hasOut = 0; hasAttn = 1; Pdst = out; }

    cudaFuncSetAttribute(attn_kernel,
                         cudaFuncAttributeMaxDynamicSharedMemorySize, ATTN_SMEM);
    cudaFuncSetAttribute(gemm_tc_kernel,
                         cudaFuncAttributeMaxDynamicSharedMemorySize, GEMM_SMEM);

    convert_kernel<<<512, 256>>>(
        (const float4*)query, (const float4*)key_, (const float4*)value,
        (const float4*)Wq, (const float4*)Wk, (const float4*)Wv,
        (const float4*)Wo, (const float4*)bq);

    // fused Q/K/V projections: 16 x 32 x 3 = 1536 CTAs
    gemm_tc_kernel<<<dim3(D_ / 64, M_ / 128, 3), 256, GEMM_SMEM>>>(
        bk, bv, nullptr, nullptr, 99);

    // attention: paired q-tiles, uniform work, single wave (256 CTAs)
    attn_kernel<<<dim3(NQT2_ / 2, BH_), 256, ATTN_SMEM>>>(Pdst, hasAttn);

    if (hasOut)
        gemm_tc_kernel<<<dim3(D_ / 64, M_ / 128, 1), 256, GEMM_SMEM>>>(
            nullptr, nullptr, bo, out, 0);
}

// round 16
// speedup vs baseline: 1.1139x; 1.0031x over previous
#include <cuda_runtime.h>
#include <cuda_fp16.h>
#include <cstdint>

// ---------------- problem constants ----------------
static constexpr int B_   = 2;
static constexpr int S_   = 2048;
static constexpr int D_   = 1024;
static constexpr int H_   = 16;
static constexpr int HD_  = 64;
static constexpr int M_   = B_ * S_;    // 4096
static constexpr int BH_  = B_ * H_;    // 32
static constexpr int QT_  = 128;
static constexpr int NQT2_ = S_ / QT_;  // 16
static constexpr float INV_SCALE = 0.125f;  // 1/sqrt(64), exact power of 2

// ---------------- device scratch (fp16) ----------------
__device__ __align__(256) __half g_xq[(size_t)M_ * D_];
__device__ __align__(256) __half g_xk[(size_t)M_ * D_];
__device__ __align__(256) __half g_xv[(size_t)M_ * D_];
__device__ __align__(256) __half g_wq[(size_t)D_ * D_];   // pre-scaled x1/8
__device__ __align__(256) __half g_wk[(size_t)D_ * D_];
__device__ __align__(256) __half g_wv[(size_t)D_ * D_];
__device__ __align__(256) __half g_wo[(size_t)D_ * D_];
__device__ __align__(256) float  g_bqs[D_];               // bq x 1/8 (fp32)
__device__ __align__(256) __half g_q [(size_t)BH_ * S_ * HD_];  // [bh][s][hd], pre-scaled
__device__ __align__(256) __half g_k [(size_t)BH_ * S_ * HD_];  // [bh][s][hd]
__device__ __align__(256) __half g_v [(size_t)BH_ * S_ * HD_];  // TRANSPOSED: [bh][hd][s]
__device__ __align__(256) __half g_ao[(size_t)M_ * D_];

// ---------------- helpers ----------------
__device__ __forceinline__ uint32_t smem_u32(const void* p) {
    uint32_t a;
    asm("{ .reg .u64 t; cvta.to.shared.u64 t, %1; cvt.u32.u64 %0, t; }" : "=r"(a) : "l"(p));
    return a;
}
__device__ __forceinline__ void cp_async16(uint32_t saddr, const void* gaddr) {
    asm volatile("cp.async.cg.shared.global [%0], [%1], 16;" :: "r"(saddr), "l"(gaddr));
}
__device__ __forceinline__ uint32_t f2h2(float x, float y) {
    __half2 h = __floats2half2_rn(x, y);
    return *(uint32_t*)&h;
}
__device__ __forceinline__ void mma16(float* c, uint32_t a0, uint32_t a1, uint32_t a2,
                                      uint32_t a3, uint32_t b0, uint32_t b1) {
    asm volatile(
        "mma.sync.aligned.m16n8k16.row.col.f32.f16.f16.f32 "
        "{%0,%1,%2,%3}, {%4,%5,%6,%7}, {%8,%9}, {%0,%1,%2,%3};"
        : "+f"(c[0]), "+f"(c[1]), "+f"(c[2]), "+f"(c[3])
        : "r"(a0), "r"(a1), "r"(a2), "r"(a3), "r"(b0), "r"(b1));
}
__device__ __forceinline__ void ldsm4(uint32_t addr, uint32_t& r0, uint32_t& r1,
                                      uint32_t& r2, uint32_t& r3) {
    asm volatile("ldmatrix.sync.aligned.m8n8.x4.shared.b16 {%0,%1,%2,%3}, [%4];"
                 : "=r"(r0), "=r"(r1), "=r"(r2), "=r"(r3) : "r"(addr));
}
__device__ __forceinline__ uint32_t lm_addr(uint32_t smemBase, int lane,
                                            int rowBase, int colBase, int strideH) {
    int lr  = lane & 7;
    int r8  = (lane >> 3) & 1;
    int c8  = lane >> 4;
    return smemBase + (uint32_t)((rowBase + lr + r8 * 8) * strideH
                                 + colBase + c8 * 8) * 2u;
}
// streaming (evict-first) 16B store
__device__ __forceinline__ void stg_cs_v4(void* ptr, float4 v) {
    asm volatile("st.global.cs.v4.f32 [%0], {%1,%2,%3,%4};"
                 :: "l"(ptr), "f"(v.x), "f"(v.y), "f"(v.z), "f"(v.w) : "memory");
}

// ============================================================
// Pre-conversion: fp32 -> fp16. Wq,bq scaled by 1/8 (exact).
// ============================================================
__global__ __launch_bounds__(256) void convert_kernel(
    const float4* __restrict__ q, const float4* __restrict__ k,
    const float4* __restrict__ v, const float4* __restrict__ wq,
    const float4* __restrict__ wk, const float4* __restrict__ wv,
    const float4* __restrict__ wo, const float4* __restrict__ bq)
{
    constexpr int NQ4 = M_ * D_ / 4;
    constexpr int NW4 = D_ * D_ / 4;
    constexpr int NB4 = D_ / 4;
    constexpr int TOT = 3 * NQ4 + 4 * NW4 + NB4;

    for (int i = blockIdx.x * blockDim.x + threadIdx.x; i < TOT;
         i += gridDim.x * blockDim.x) {
        int j = i;
        const float4* src; __half* dsth = nullptr; float sc = 1.f;
        if (j < NQ4)                    { src = q;  dsth = g_xq; }
        else if ((j -= NQ4) < NQ4)      { src = k;  dsth = g_xk; }
        else if ((j -= NQ4) < NQ4)      { src = v;  dsth = g_xv; }
        else if ((j -= NQ4) < NW4)      { src = wq; dsth = g_wq; sc = INV_SCALE; }
        else if ((j -= NW4) < NW4)      { src = wk; dsth = g_wk; }
        else if ((j -= NW4) < NW4)      { src = wv; dsth = g_wv; }
        else if ((j -= NW4) < NW4)      { src = wo; dsth = g_wo; }
        else {
            j -= NW4;
            float4 s = bq[j];
            ((float4*)g_bqs)[j] = make_float4(s.x * INV_SCALE, s.y * INV_SCALE,
                                              s.z * INV_SCALE, s.w * INV_SCALE);
            continue;
        }
        float4 s = src[j];
        uint2 o = make_uint2(f2h2(s.x * sc, s.y * sc), f2h2(s.z * sc, s.w * sc));
        ((uint2*)dsth)[j] = o;
    }
}

// ============================================================
// fp16 mma GEMM: CTA tile 128(M) x 64(N), 8 warps (4m x 2n),
// warp tile 32x32. BK=32, 4-buffer single-sync pipeline. 3 CTAs/SM.
// mode 3 (V projection): epilogue via SMEM TRANSPOSE -> coalesced
// stores along S (was: 8192 scattered 2B stores per CTA).
// ============================================================
static constexpr int SAH = 40;                            // halfs/row (80B: LDSM conflict-free)
static constexpr int GEMM_SMEM = 4 * 192 * SAH * 2;       // 61440 B
static constexpr int TSP_STRIDE = 136;                    // halfs; 272B = 17x16B (aligned, bank-safe)

__global__ __launch_bounds__(256, 3) void gemm_tc_kernel(
    const float* __restrict__ biasK, const float* __restrict__ biasV,
    const float* __restrict__ biasO, float* __restrict__ outPlain, int modeParam)
{
    extern __shared__ __half smh[];

    const int mode = (modeParam == 99) ? (int)blockIdx.z + 1 : modeParam;
    const __half* A = (mode == 1) ? g_xq : (mode == 2) ? g_xk
                    : (mode == 3) ? g_xv : g_ao;
    const __half* W = (mode == 1) ? g_wq : (mode == 2) ? g_wk
                    : (mode == 3) ? g_wv : g_wo;
    const float* bias = (mode == 1) ? g_bqs : (mode == 2) ? biasK
                      : (mode == 3) ? biasV : biasO;

    const int tid  = threadIdx.x;
    const int lane = tid & 31;
    const int w    = tid >> 5;
    const int gg   = lane >> 2;
    const int t4   = lane & 3;
    const int wm   = w & 3;    // 4 m-slices of 32 rows
    const int wn   = w >> 2;   // 2 n-slices of 32 cols
    const int rowBase = blockIdx.y * 128;
    const int colBase = blockIdx.x * 64;
    const int K = D_;

    const uint32_t sBase = smem_u32(smh);

    // buffer b: A (128 rows) at b*192*SAH, B (64 rows) at +128*SAH
    auto stage = [&](int st, int k0) {
#pragma unroll
        for (int ii = 0; ii < 2; ii++) {
            int idx = tid + ii * 256;
            int row = idx >> 2, ch = (idx & 3) * 8;
            uint32_t off = (uint32_t)(st * 192 * SAH + row * SAH + ch) * 2u;
            cp_async16(sBase + off, &A[(size_t)(rowBase + row) * K + k0 + ch]);
        }
        {
            int row = tid >> 2, ch = (tid & 3) * 8;
            uint32_t off = (uint32_t)(st * 192 * SAH + (128 + row) * SAH + ch) * 2u;
            cp_async16(sBase + off, &W[(size_t)(colBase + row) * K + k0 + ch]);
        }
        asm volatile("cp.async.commit_group;" ::: "memory");
    };

    float c[2][4][4];
#pragma unroll
    for (int i = 0; i < 2; i++)
#pragma unroll
        for (int j = 0; j < 4; j++)
#pragma unroll
            for (int q = 0; q < 4; q++) c[i][j][q] = 0.f;

    const int NCH = K / 32;  // 32 chunks
    stage(0, 0);
    stage(1, 32);
    stage(2, 64);

    for (int ch = 0; ch < NCH; ch++) {
        const int rem = NCH - 1 - ch;
        if (rem >= 2)      asm volatile("cp.async.wait_group 2;" ::: "memory");
        else if (rem == 1) asm volatile("cp.async.wait_group 1;" ::: "memory");
        else               asm volatile("cp.async.wait_group 0;" ::: "memory");
        __syncthreads();
        if (ch + 3 < NCH) stage((ch + 3) % 4, (ch + 3) * 32);

        const uint32_t aB = sBase + (uint32_t)((ch % 4) * 192 * SAH) * 2u;
        const uint32_t bB = aB + 128 * SAH * 2;
#pragma unroll
        for (int kk = 0; kk < 32; kk += 16) {
            uint32_t af[2][4], bf[4][2];
#pragma unroll
            for (int i = 0; i < 2; i++)
                ldsm4(lm_addr(aB, lane, wm * 32 + i * 16, kk, SAH),
                      af[i][0], af[i][1], af[i][2], af[i][3]);
#pragma unroll
            for (int jp = 0; jp < 2; jp++)
                ldsm4(lm_addr(bB, lane, wn * 32 + jp * 16, kk, SAH),
                      bf[jp * 2][0], bf[jp * 2 + 1][0], bf[jp * 2][1], bf[jp * 2 + 1][1]);
#pragma unroll
            for (int i = 0; i < 2; i++)
#pragma unroll
                for (int j = 0; j < 4; j++)
                    mma16(c[i][j], af[i][0], af[i][1], af[i][2], af[i][3],
                          bf[j][0], bf[j][1]);
        }
    }

    if (mode == 3) {
        // V projection: transpose tile in smem, store coalesced along S.
        __syncthreads();   // all warps done reading stage buffers
        __half* tsp = smh; // [64 cols][TSP_STRIDE] halfs = 17408 B
#pragma unroll
        for (int i = 0; i < 2; i++) {
#pragma unroll
            for (int j = 0; j < 4; j++) {
                int cl = wn * 32 + j * 8 + 2 * t4;
                float2 b2 = *(const float2*)&bias[colBase + cl];
#pragma unroll
                for (int h = 0; h < 2; h++) {
                    int ml = wm * 32 + i * 16 + gg + h * 8;
                    tsp[cl * TSP_STRIDE + ml]       = __float2half_rn(c[i][j][h * 2 + 0] + b2.x);
                    tsp[(cl + 1) * TSP_STRIDE + ml] = __float2half_rn(c[i][j][h * 2 + 1] + b2.y);
                }
            }
        }
        __syncthreads();
        const int bb  = rowBase >> 11;
        const int hh  = colBase >> 6;
        const int ss0 = rowBase & (S_ - 1);
        __half* gv = g_v + ((size_t)(bb * H_ + hh)) * HD_ * S_;
#pragma unroll
        for (int k2 = 0; k2 < 4; k2++) {
            int u   = tid + k2 * 256;      // 0..1023 16B-units
            int col = u >> 4, seg = u & 15;
            uint4 vv = *(const uint4*)&tsp[col * TSP_STRIDE + seg * 8];
            *(uint4*)&gv[(size_t)col * S_ + ss0 + seg * 8] = vv;
        }
        return;
    }

#pragma unroll
    for (int i = 0; i < 2; i++) {
#pragma unroll
        for (int j = 0; j < 4; j++) {
            int r0  = rowBase + wm * 32 + i * 16 + gg;
            int col = colBase + wn * 32 + j * 8 + 2 * t4;
            float2 b2 = *(const float2*)&bias[col];
#pragma unroll
            for (int h = 0; h < 2; h++) {
                int m = r0 + h * 8;
                float x = c[i][j][h * 2 + 0] + b2.x;
                float y = c[i][j][h * 2 + 1] + b2.y;
                if (mode == 0) {
                    *(float2*)&outPlain[(size_t)m * D_ + col] = make_float2(x, y);
                } else {
                    int bb = m >> 11, ss = m & (S_ - 1);
                    int hh = col >> 6, hd = col & 63;
                    __half* tgt = (mode == 1) ? g_q : g_k;
                    *(uint32_t*)&tgt[(((size_t)(bb * H_ + hh)) * S_ + ss) * HD_ + hd] =
                        f2h2(x, y);
                }
            }
        }
    }
}

// ============================================================
// Fused causal attention (fp16 MMA + ldmatrix), two sweeps,
// PAIRED q-tiles per CTA (uniform 34 k-tiles, one wave),
// triple-buffered K / K+V, single-sync pipeline.
// P writes use st.global.cs (streaming, evict-first).
// ============================================================
static constexpr int SQ_  = 68;   // E32 float stride
static constexpr int SH_  = 72;   // half-row stride (144B: LDSM conflict-free)
static constexpr int OFF_EH  = 128 * SQ_ * 4;            // 34816
static constexpr int OFF_K   = OFF_EH + 128 * SH_ * 2;   // 53248
static constexpr int OFF_V   = OFF_K + 3 * 64 * SH_ * 2; // 80896
static constexpr int OFF_INV = OFF_V + 3 * 64 * SH_ * 2; // 108544
static constexpr int ATTN_SMEM = OFF_INV + 128 * 4;      // 109056 B

__global__ __launch_bounds__(256, 2) void attn_kernel(float* __restrict__ P, int writeP)
{
    extern __shared__ char smc[];
    float*  E32   = (float*)smc;
    __half* Qh    = (__half*)smc;            // aliases E32 during Q staging
    __half* Eh    = (__half*)(smc + OFF_EH);
    __half* Kdb   = (__half*)(smc + OFF_K);
    __half* Vdb   = (__half*)(smc + OFF_V);
    float*  inv_s = (float*)(smc + OFF_INV);
    float*  rsc   = (float*)Vdb;             // rowsum scratch (between sweeps only)

    const int tid  = threadIdx.x;
    const int lane = tid & 31;
    const int w    = tid >> 5;
    const int gg   = lane >> 2;
    const int t4   = lane & 3;
    const int wm   = w & 3;
    const int wn   = w >> 2;
    const int bh   = blockIdx.y;

    const __half* Qg = g_q + (size_t)bh * S_ * HD_;
    const __half* Kg = g_k + (size_t)bh * S_ * HD_;
    const __half* Vg = g_v + (size_t)bh * S_ * HD_;   // [hd][s]

    const uint32_t sQ = smem_u32(Qh);
    const uint32_t sE = smem_u32(Eh);
    const uint32_t sK = smem_u32(Kdb);
    const uint32_t sV = smem_u32(Vdb);

    auto stageK = [&](int b, int k0) {
#pragma unroll
        for (int i = 0; i < 2; i++) {
            int idx = tid + i * 256;
            int row = idx >> 3, c = (idx & 7) * 8;
            cp_async16(sK + (uint32_t)(b * 64 * SH_ + row * SH_ + c) * 2u,
                       &Kg[(size_t)(k0 + row) * HD_ + c]);
        }
    };
    auto stageV = [&](int b, int k0) {
#pragma unroll
        for (int i = 0; i < 2; i++) {
            int idx = tid + i * 256;
            int row = idx >> 3, c = (idx & 7) * 8;
            cp_async16(sV + (uint32_t)(b * 64 * SH_ + row * SH_ + c) * 2u,
                       &Vg[(size_t)row * S_ + k0 + c]);
        }
    };

#pragma unroll 1
    for (int p = 0; p < 2; p++) {
        const int qt = p == 0 ? (NQT2_ - 1) - (int)blockIdx.x : (int)blockIdx.x;
        const int q0 = qt * QT_;
        __syncthreads();  // previous pair fully done

        // stage Q tile (fp16, pre-scaled)
#pragma unroll
        for (int i = 0; i < 4; i++) {
            int idx = tid + i * 256;
            int row = idx >> 3, c = (idx & 7) * 8;
            cp_async16(sQ + (uint32_t)(row * SH_ + c) * 2u,
                       &Qg[(size_t)(q0 + row) * HD_ + c]);
        }
        asm volatile("cp.async.commit_group;" ::: "memory");
        asm volatile("cp.async.wait_group 0;" ::: "memory");
        __syncthreads();

        // Q fragments -> registers via ldmatrix
        uint32_t qf[4][8];
#pragma unroll
        for (int ck = 0; ck < 4; ck++)
#pragma unroll
            for (int i = 0; i < 2; i++)
                ldsm4(lm_addr(sQ, lane, wm * 32 + i * 16, ck * 16, SH_),
                      qf[ck][i * 4 + 0], qf[ck][i * 4 + 1],
                      qf[ck][i * 4 + 2], qf[ck][i * 4 + 3]);
        __syncthreads();  // Q region now free (E32 aliases it)

        const int nkt = 2 * qt + 2;  // >= 2 always

        // ================= sweep 1: rowsums (3-buffer K, 1 sync/iter) ====
        stageK(0, 0);
        asm volatile("cp.async.commit_group;" ::: "memory");
        stageK(1, 64);
        asm volatile("cp.async.commit_group;" ::: "memory");

        float rs[2][2] = {{0.f, 0.f}, {0.f, 0.f}};
        for (int kt = 0; kt < nkt; kt++) {
            if (kt + 1 < nkt) asm volatile("cp.async.wait_group 1;" ::: "memory");
            else              asm volatile("cp.async.wait_group 0;" ::: "memory");
            __syncthreads();  // K(kt) visible + all warps done with buf (kt-1)%3
            if (kt + 2 < nkt) {
                stageK((kt + 2) % 3, (kt + 2) * 64);
                asm volatile("cp.async.commit_group;" ::: "memory");
            }

            const uint32_t kB = sK + (uint32_t)((kt % 3) * 64 * SH_) * 2u;
            float s[2][4][4];
#pragma unroll
            for (int i = 0; i < 2; i++)
#pragma unroll
                for (int j = 0; j < 4; j++)
#pragma unroll
                    for (int q = 0; q < 4; q++) s[i][j][q] = 0.f;
#pragma unroll
            for (int ck = 0; ck < 4; ck++) {
                uint32_t bf[4][2];
#pragma unroll
                for (int jp = 0; jp < 2; jp++)
                    ldsm4(lm_addr(kB, lane, wn * 32 + jp * 16, ck * 16, SH_),
                          bf[jp * 2][0], bf[jp * 2 + 1][0],
                          bf[jp * 2][1], bf[jp * 2 + 1][1]);
#pragma unroll
                for (int i = 0; i < 2; i++)
#pragma unroll
                    for (int j = 0; j < 4; j++)
                        mma16(s[i][j], qf[ck][i * 4 + 0], qf[ck][i * 4 + 1],
                              qf[ck][i * 4 + 2], qf[ck][i * 4 + 3], bf[j][0], bf[j][1]);
            }

            const int k0 = kt * 64;
            if (k0 + 63 <= q0 + wm * 32) {
#pragma unroll
                for (int i = 0; i < 2; i++)
#pragma unroll
                    for (int j = 0; j < 4; j++) {
                        rs[i][0] += __expf(s[i][j][0]) + __expf(s[i][j][1]);
                        rs[i][1] += __expf(s[i][j][2]) + __expf(s[i][j][3]);
                    }
            } else {
#pragma unroll
                for (int i = 0; i < 2; i++) {
                    int qiA = q0 + wm * 32 + i * 16 + gg, qiB = qiA + 8;
#pragma unroll
                    for (int j = 0; j < 4; j++) {
                        int ki0 = k0 + wn * 32 + j * 8 + 2 * t4, ki1 = ki0 + 1;
                        rs[i][0] += ((ki0 <= qiA) ? __expf(s[i][j][0]) : 0.f)
                                  + ((ki1 <= qiA) ? __expf(s[i][j][1]) : 0.f);
                        rs[i][1] += ((ki0 <= qiB) ? __expf(s[i][j][2]) : 0.f)
                                  + ((ki1 <= qiB) ? __expf(s[i][j][3]) : 0.f);
                    }
                }
            }
        }
#pragma unroll
        for (int i = 0; i < 2; i++) {
#pragma unroll
            for (int h = 0; h < 2; h++) {
                rs[i][h] += __shfl_xor_sync(0xFFFFFFFF, rs[i][h], 1);
                rs[i][h] += __shfl_xor_sync(0xFFFFFFFF, rs[i][h], 2);
            }
        }
        __syncthreads();
        if (t4 == 0) {
#pragma unroll
            for (int i = 0; i < 2; i++) {
                int r0 = wm * 32 + i * 16 + gg;
                rsc[wn * 128 + r0]     = rs[i][0];
                rsc[wn * 128 + r0 + 8] = rs[i][1];
            }
        }
        __syncthreads();
        if (tid < 128) inv_s[tid] = 1.f / (rsc[tid] + rsc[128 + tid]);
        __syncthreads();  // rsc reads done before V restaging below

        // ================= sweep 2: P + O (3-buffer K+V) =================
        float o[2][4][4];
#pragma unroll
        for (int i = 0; i < 2; i++)
#pragma unroll
            for (int j = 0; j < 4; j++)
#pragma unroll
                for (int q = 0; q < 4; q++) o[i][j][q] = 0.f;

        stageK(0, 0); stageV(0, 0);
        asm volatile("cp.async.commit_group;" ::: "memory");
        stageK(1, 64); stageV(1, 64);
        asm volatile("cp.async.commit_group;" ::: "memory");

        for (int kt = 0; kt < S_ / 64; kt++) {
            const int k0 = kt * 64;
            if (kt < nkt) {
                if (kt + 1 < nkt) asm volatile("cp.async.wait_group 1;" ::: "memory");
                else              asm volatile("cp.async.wait_group 0;" ::: "memory");
                __syncthreads();  // K/V(kt) visible + iter kt-1 fully consumed
                if (kt + 2 < nkt) {
                    stageK((kt + 2) % 3, (kt + 2) * 64);
                    stageV((kt + 2) % 3, (kt + 2) * 64);
                    asm volatile("cp.async.commit_group;" ::: "memory");
                }

                const uint32_t kB = sK + (uint32_t)((kt % 3) * 64 * SH_) * 2u;
                const uint32_t vB = sV + (uint32_t)((kt % 3) * 64 * SH_) * 2u;

                float s[2][4][4];
#pragma unroll
                for (int i = 0; i < 2; i++)
#pragma unroll
                    for (int j = 0; j < 4; j++)
#pragma unroll
                        for (int q = 0; q < 4; q++) s[i][j][q] = 0.f;
#pragma unroll
                for (int ck = 0; ck < 4; ck++) {
                    uint32_t bf[4][2];
#pragma unroll
                    for (int jp = 0; jp < 2; jp++)
                        ldsm4(lm_addr(kB, lane, wn * 32 + jp * 16, ck * 16, SH_),
                              bf[jp * 2][0], bf[jp * 2 + 1][0],
                              bf[jp * 2][1], bf[jp * 2 + 1][1]);
#pragma unroll
                    for (int i = 0; i < 2; i++)
#pragma unroll
                        for (int j = 0; j < 4; j++)
                            mma16(s[i][j], qf[ck][i * 4 + 0], qf[ck][i * 4 + 1],
                                  qf[ck][i * 4 + 2], qf[ck][i * 4 + 3],
                                  bf[j][0], bf[j][1]);
                }

                // e_norm = exp * inv, masked only on edge tiles
#pragma unroll
                for (int i = 0; i < 2; i++) {
                    int r0 = wm * 32 + i * 16 + gg;
                    float invA = inv_s[r0], invB = inv_s[r0 + 8];
                    if (k0 + 63 <= q0 + wm * 32) {
#pragma unroll
                        for (int j = 0; j < 4; j++) {
                            s[i][j][0] = __expf(s[i][j][0]) * invA;
                            s[i][j][1] = __expf(s[i][j][1]) * invA;
                            s[i][j][2] = __expf(s[i][j][2]) * invB;
                            s[i][j][3] = __expf(s[i][j][3]) * invB;
                        }
                    } else {
                        int qiA = q0 + r0, qiB = qiA + 8;
#pragma unroll
                        for (int j = 0; j < 4; j++) {
                            int ki0 = k0 + wn * 32 + j * 8 + 2 * t4, ki1 = ki0 + 1;
                            s[i][j][0] = (ki0 <= qiA) ? __expf(s[i][j][0]) * invA : 0.f;
                            s[i][j][1] = (ki1 <= qiA) ? __expf(s[i][j][1]) * invA : 0.f;
                            s[i][j][2] = (ki0 <= qiB) ? __expf(s[i][j][2]) * invB : 0.f;
                            s[i][j][3] = (ki1 <= qiB) ? __expf(s[i][j][3]) * invB : 0.f;
                        }
                    }
                }

                // dual-store E: fp16 for MMA, fp32 for coalesced P write
#pragma unroll
                for (int i = 0; i < 2; i++) {
                    int r0 = wm * 32 + i * 16 + gg;
#pragma unroll
                    for (int j = 0; j < 4; j++) {
                        int cl = wn * 32 + j * 8 + 2 * t4;
                        *(uint32_t*)&Eh[r0 * SH_ + cl]       = f2h2(s[i][j][0], s[i][j][1]);
                        *(uint32_t*)&Eh[(r0 + 8) * SH_ + cl] = f2h2(s[i][j][2], s[i][j][3]);
                        if (writeP) {
                            *(float2*)&E32[r0 * SQ_ + cl] =
                                make_float2(s[i][j][0], s[i][j][1]);
                            *(float2*)&E32[(r0 + 8) * SQ_ + cl] =
                                make_float2(s[i][j][2], s[i][j][3]);
                        }
                    }
                }
                __syncthreads();  // E complete

                if (writeP) {
                    float* Pd = P + (size_t)bh * S_ * S_ + (size_t)q0 * S_ + k0;
#pragma unroll
                    for (int i = 0; i < 8; i++) {
                        int idx = tid + i * 256;
                        int row = idx >> 4, cc = (idx & 15) * 4;
                        float4 v = *(const float4*)&E32[row * SQ_ + cc];
                        stg_cs_v4(&Pd[(size_t)row * S_ + cc], v);
                    }
                }

                // O += E_norm @ V
#pragma unroll
                for (int ck = 0; ck < 4; ck++) {
                    uint32_t af[2][4], bf[4][2];
#pragma unroll
                    for (int i = 0; i < 2; i++)
                        ldsm4(lm_addr(sE, lane, wm * 32 + i * 16, ck * 16, SH_),
                              af[i][0], af[i][1], af[i][2], af[i][3]);
#pragma unroll
                    for (int jp = 0; jp < 2; jp++)
                        ldsm4(lm_addr(vB, lane, wn * 32 + jp * 16, ck * 16, SH_),
                              bf[jp * 2][0], bf[jp * 2 + 1][0],
                              bf[jp * 2][1], bf[jp * 2 + 1][1]);
#pragma unroll
                    for (int i = 0; i < 2; i++)
#pragma unroll
                        for (int j = 0; j < 4; j++)
                            mma16(o[i][j], af[i][0], af[i][1], af[i][2], af[i][3],
                                  bf[j][0], bf[j][1]);
                }
            } else if (writeP) {
                float* Pd = P + (size_t)bh * S_ * S_ + (size_t)q0 * S_ + k0;
                const float4 z = make_float4(0.f, 0.f, 0.f, 0.f);
#pragma unroll
                for (int i = 0; i < 8; i++) {
                    int idx = tid + i * 256;
                    int row = idx >> 4, cc = (idx & 15) * 4;
                    stg_cs_v4(&Pd[(size_t)row * S_ + cc], z);
                }
            }
        }

        // epilogue: O -> g_ao (fp16)
        const int bb = bh >> 4, hh = bh & 15;
#pragma unroll
        for (int i = 0; i < 2; i++) {
            int r0 = wm * 32 + i * 16 + gg;
            int mA = bb * S_ + q0 + r0;
#pragma unroll
            for (int j = 0; j < 4; j++) {
                int cl = hh * 64 + wn * 32 + j * 8 + 2 * t4;
                *(uint32_t*)&g_ao[(size_t)mA * D_ + cl]       = f2h2(o[i][j][0], o[i][j][1]);
                *(uint32_t*)&g_ao[(size_t)(mA + 8) * D_ + cl] = f2h2(o[i][j][2], o[i][j][3]);
            }
        }
    }
}

// ============================================================
extern "C" void kernel_launch(void* const* d_in, const int* in_sizes, int n_in,
                              void* d_out, int out_size)
{
    const float* query = (const float*)d_in[0];
    const float* key_  = (const float*)d_in[1];
    const float* value = (const float*)d_in[2];
    // d_in[3] = causal mask — handled analytically
    const float* Wq = (const float*)d_in[4];
    const float* bq = (const float*)d_in[5];
    const float* Wk = (const float*)d_in[6];
    const float* bk = (const float*)d_in[7];
    const float* Wv = (const float*)d_in[8];
    const float* bv = (const float*)d_in[9];
    const float* Wo = (const float*)d_in[10];
    const float* bo = (const float*)d_in[11];
    float* out = (float*)d_out;

    const long long outN  = (long long)M_ * D_;
    const long long attnN = (long long)BH_ * S_ * S_;

    int hasOut = 1, hasAttn = 0;
    float* Pdst = nullptr;
    if ((long long)out_size >= outN + attnN) { hasAttn = 1; Pdst = out + outN; }
    else if ((long long)out_size == attnN)   { hasOut = 0; hasAttn = 1; Pdst = out; }

    cudaFuncSetAttribute(attn_kernel,
                         cudaFuncAttributeMaxDynamicSharedMemorySize, ATTN_SMEM);
    cudaFuncSetAttribute(gemm_tc_kernel,
                         cudaFuncAttributeMaxDynamicSharedMemorySize, GEMM_SMEM);

    convert_kernel<<<512, 256>>>(
        (const float4*)query, (const float4*)key_, (const float4*)value,
        (const float4*)Wq, (const float4*)Wk, (const float4*)Wv,
        (const float4*)Wo, (const float4*)bq);

    // fused Q/K/V projections: 16 x 32 x 3 = 1536 CTAs
    gemm_tc_kernel<<<dim3(D_ / 64, M_ / 128, 3), 256, GEMM_SMEM>>>(
        bk, bv, nullptr, nullptr, 99);

    // attention: paired q-tiles, uniform work, single wave (256 CTAs)
    attn_kernel<<<dim3(NQT2_ / 2, BH_), 256, ATTN_SMEM>>>(Pdst, hasAttn);

    if (hasOut)
        gemm_tc_kernel<<<dim3(D_ / 64, M_ / 128, 1), 256, GEMM_SMEM>>>(
            nullptr, nullptr, bo, out, 0);
}

// round 17
// speedup vs baseline: 1.1157x; 1.0016x over previous
#include <cuda_runtime.h>
#include <cuda_fp16.h>
#include <cstdint>

// ---------------- problem constants ----------------
static constexpr int B_   = 2;
static constexpr int S_   = 2048;
static constexpr int D_   = 1024;
static constexpr int H_   = 16;
static constexpr int HD_  = 64;
static constexpr int M_   = B_ * S_;    // 4096
static constexpr int BH_  = B_ * H_;    // 32
static constexpr int QT_  = 128;
static constexpr int NQT2_ = S_ / QT_;  // 16
static constexpr float INV_SCALE = 0.125f;  // 1/sqrt(64), exact power of 2

// ---------------- device scratch (fp16) ----------------
__device__ __align__(256) __half g_xq[(size_t)M_ * D_];
__device__ __align__(256) __half g_xk[(size_t)M_ * D_];
__device__ __align__(256) __half g_xv[(size_t)M_ * D_];
__device__ __align__(256) __half g_wq[(size_t)D_ * D_];   // pre-scaled x1/8
__device__ __align__(256) __half g_wk[(size_t)D_ * D_];
__device__ __align__(256) __half g_wv[(size_t)D_ * D_];
__device__ __align__(256) __half g_wo[(size_t)D_ * D_];
__device__ __align__(256) float  g_bqs[D_];               // bq x 1/8 (fp32)
__device__ __align__(256) __half g_q [(size_t)BH_ * S_ * HD_];  // [bh][s][hd], pre-scaled
__device__ __align__(256) __half g_k [(size_t)BH_ * S_ * HD_];  // [bh][s][hd]
__device__ __align__(256) __half g_v [(size_t)BH_ * S_ * HD_];  // TRANSPOSED: [bh][hd][s]
__device__ __align__(256) __half g_ao[(size_t)M_ * D_];

// ---------------- helpers ----------------
__device__ __forceinline__ uint32_t smem_u32(const void* p) {
    uint32_t a;
    asm("{ .reg .u64 t; cvta.to.shared.u64 t, %1; cvt.u32.u64 %0, t; }" : "=r"(a) : "l"(p));
    return a;
}
__device__ __forceinline__ void cp_async16(uint32_t saddr, const void* gaddr) {
    asm volatile("cp.async.cg.shared.global [%0], [%1], 16;" :: "r"(saddr), "l"(gaddr));
}
__device__ __forceinline__ uint32_t f2h2(float x, float y) {
    __half2 h = __floats2half2_rn(x, y);
    return *(uint32_t*)&h;
}
__device__ __forceinline__ void mma16(float* c, uint32_t a0, uint32_t a1, uint32_t a2,
                                      uint32_t a3, uint32_t b0, uint32_t b1) {
    asm volatile(
        "mma.sync.aligned.m16n8k16.row.col.f32.f16.f16.f32 "
        "{%0,%1,%2,%3}, {%4,%5,%6,%7}, {%8,%9}, {%0,%1,%2,%3};"
        : "+f"(c[0]), "+f"(c[1]), "+f"(c[2]), "+f"(c[3])
        : "r"(a0), "r"(a1), "r"(a2), "r"(a3), "r"(b0), "r"(b1));
}
__device__ __forceinline__ void ldsm4(uint32_t addr, uint32_t& r0, uint32_t& r1,
                                      uint32_t& r2, uint32_t& r3) {
    asm volatile("ldmatrix.sync.aligned.m8n8.x4.shared.b16 {%0,%1,%2,%3}, [%4];"
                 : "=r"(r0), "=r"(r1), "=r"(r2), "=r"(r3) : "r"(addr));
}
__device__ __forceinline__ uint32_t lm_addr(uint32_t smemBase, int lane,
                                            int rowBase, int colBase, int strideH) {
    int lr  = lane & 7;
    int r8  = (lane >> 3) & 1;
    int c8  = lane >> 4;
    return smemBase + (uint32_t)((rowBase + lr + r8 * 8) * strideH
                                 + colBase + c8 * 8) * 2u;
}
// streaming (evict-first) 16B store
__device__ __forceinline__ void stg_cs_v4(void* ptr, float4 v) {
    asm volatile("st.global.cs.v4.f32 [%0], {%1,%2,%3,%4};"
                 :: "l"(ptr), "f"(v.x), "f"(v.y), "f"(v.z), "f"(v.w) : "memory");
}

// ============================================================
// Pre-conversion: fp32 -> fp16. Wq,bq scaled by 1/8 (exact).
// ============================================================
__global__ __launch_bounds__(256) void convert_kernel(
    const float4* __restrict__ q, const float4* __restrict__ k,
    const float4* __restrict__ v, const float4* __restrict__ wq,
    const float4* __restrict__ wk, const float4* __restrict__ wv,
    const float4* __restrict__ wo, const float4* __restrict__ bq)
{
    constexpr int NQ4 = M_ * D_ / 4;
    constexpr int NW4 = D_ * D_ / 4;
    constexpr int NB4 = D_ / 4;
    constexpr int TOT = 3 * NQ4 + 4 * NW4 + NB4;

    for (int i = blockIdx.x * blockDim.x + threadIdx.x; i < TOT;
         i += gridDim.x * blockDim.x) {
        int j = i;
        const float4* src; __half* dsth = nullptr; float sc = 1.f;
        if (j < NQ4)                    { src = q;  dsth = g_xq; }
        else if ((j -= NQ4) < NQ4)      { src = k;  dsth = g_xk; }
        else if ((j -= NQ4) < NQ4)      { src = v;  dsth = g_xv; }
        else if ((j -= NQ4) < NW4)      { src = wq; dsth = g_wq; sc = INV_SCALE; }
        else if ((j -= NW4) < NW4)      { src = wk; dsth = g_wk; }
        else if ((j -= NW4) < NW4)      { src = wv; dsth = g_wv; }
        else if ((j -= NW4) < NW4)      { src = wo; dsth = g_wo; }
        else {
            j -= NW4;
            float4 s = bq[j];
            ((float4*)g_bqs)[j] = make_float4(s.x * INV_SCALE, s.y * INV_SCALE,
                                              s.z * INV_SCALE, s.w * INV_SCALE);
            continue;
        }
        float4 s = src[j];
        uint2 o = make_uint2(f2h2(s.x * sc, s.y * sc), f2h2(s.z * sc, s.w * sc));
        ((uint2*)dsth)[j] = o;
    }
}

// ============================================================
// fp16 mma GEMM: CTA tile 128(M) x 64(N), 8 warps (4m x 2n),
// warp tile 32x32. BK=32, 4-buffer single-sync pipeline. 3 CTAs/SM.
// mode 3 (V projection): epilogue via SMEM TRANSPOSE.
// ============================================================
static constexpr int SAH = 40;                            // halfs/row (80B: LDSM conflict-free)
static constexpr int GEMM_SMEM = 4 * 192 * SAH * 2;       // 61440 B
static constexpr int TSP_STRIDE = 136;

__global__ __launch_bounds__(256, 3) void gemm_tc_kernel(
    const float* __restrict__ biasK, const float* __restrict__ biasV,
    const float* __restrict__ biasO, float* __restrict__ outPlain, int modeParam)
{
    extern __shared__ __half smh[];

    const int mode = (modeParam == 99) ? (int)blockIdx.z + 1 : modeParam;
    const __half* A = (mode == 1) ? g_xq : (mode == 2) ? g_xk
                    : (mode == 3) ? g_xv : g_ao;
    const __half* W = (mode == 1) ? g_wq : (mode == 2) ? g_wk
                    : (mode == 3) ? g_wv : g_wo;
    const float* bias = (mode == 1) ? g_bqs : (mode == 2) ? biasK
                      : (mode == 3) ? biasV : biasO;

    const int tid  = threadIdx.x;
    const int lane = tid & 31;
    const int w    = tid >> 5;
    const int gg   = lane >> 2;
    const int t4   = lane & 3;
    const int wm   = w & 3;
    const int wn   = w >> 2;
    const int rowBase = blockIdx.y * 128;
    const int colBase = blockIdx.x * 64;
    const int K = D_;

    const uint32_t sBase = smem_u32(smh);

    auto stage = [&](int st, int k0) {
#pragma unroll
        for (int ii = 0; ii < 2; ii++) {
            int idx = tid + ii * 256;
            int row = idx >> 2, ch = (idx & 3) * 8;
            uint32_t off = (uint32_t)(st * 192 * SAH + row * SAH + ch) * 2u;
            cp_async16(sBase + off, &A[(size_t)(rowBase + row) * K + k0 + ch]);
        }
        {
            int row = tid >> 2, ch = (tid & 3) * 8;
            uint32_t off = (uint32_t)(st * 192 * SAH + (128 + row) * SAH + ch) * 2u;
            cp_async16(sBase + off, &W[(size_t)(colBase + row) * K + k0 + ch]);
        }
        asm volatile("cp.async.commit_group;" ::: "memory");
    };

    float c[2][4][4];
#pragma unroll
    for (int i = 0; i < 2; i++)
#pragma unroll
        for (int j = 0; j < 4; j++)
#pragma unroll
            for (int q = 0; q < 4; q++) c[i][j][q] = 0.f;

    const int NCH = K / 32;
    stage(0, 0);
    stage(1, 32);
    stage(2, 64);

    for (int ch = 0; ch < NCH; ch++) {
        const int rem = NCH - 1 - ch;
        if (rem >= 2)      asm volatile("cp.async.wait_group 2;" ::: "memory");
        else if (rem == 1) asm volatile("cp.async.wait_group 1;" ::: "memory");
        else               asm volatile("cp.async.wait_group 0;" ::: "memory");
        __syncthreads();
        if (ch + 3 < NCH) stage((ch + 3) % 4, (ch + 3) * 32);

        const uint32_t aB = sBase + (uint32_t)((ch % 4) * 192 * SAH) * 2u;
        const uint32_t bB = aB + 128 * SAH * 2;
#pragma unroll
        for (int kk = 0; kk < 32; kk += 16) {
            uint32_t af[2][4], bf[4][2];
#pragma unroll
            for (int i = 0; i < 2; i++)
                ldsm4(lm_addr(aB, lane, wm * 32 + i * 16, kk, SAH),
                      af[i][0], af[i][1], af[i][2], af[i][3]);
#pragma unroll
            for (int jp = 0; jp < 2; jp++)
                ldsm4(lm_addr(bB, lane, wn * 32 + jp * 16, kk, SAH),
                      bf[jp * 2][0], bf[jp * 2 + 1][0], bf[jp * 2][1], bf[jp * 2 + 1][1]);
#pragma unroll
            for (int i = 0; i < 2; i++)
#pragma unroll
                for (int j = 0; j < 4; j++)
                    mma16(c[i][j], af[i][0], af[i][1], af[i][2], af[i][3],
                          bf[j][0], bf[j][1]);
        }
    }

    if (mode == 3) {
        __syncthreads();
        __half* tsp = smh;
#pragma unroll
        for (int i = 0; i < 2; i++) {
#pragma unroll
            for (int j = 0; j < 4; j++) {
                int cl = wn * 32 + j * 8 + 2 * t4;
                float2 b2 = *(const float2*)&bias[colBase + cl];
#pragma unroll
                for (int h = 0; h < 2; h++) {
                    int ml = wm * 32 + i * 16 + gg + h * 8;
                    tsp[cl * TSP_STRIDE + ml]       = __float2half_rn(c[i][j][h * 2 + 0] + b2.x);
                    tsp[(cl + 1) * TSP_STRIDE + ml] = __float2half_rn(c[i][j][h * 2 + 1] + b2.y);
                }
            }
        }
        __syncthreads();
        const int bb  = rowBase >> 11;
        const int hh  = colBase >> 6;
        const int ss0 = rowBase & (S_ - 1);
        __half* gv = g_v + ((size_t)(bb * H_ + hh)) * HD_ * S_;
#pragma unroll
        for (int k2 = 0; k2 < 4; k2++) {
            int u   = tid + k2 * 256;
            int col = u >> 4, seg = u & 15;
            uint4 vv = *(const uint4*)&tsp[col * TSP_STRIDE + seg * 8];
            *(uint4*)&gv[(size_t)col * S_ + ss0 + seg * 8] = vv;
        }
        return;
    }

#pragma unroll
    for (int i = 0; i < 2; i++) {
#pragma unroll
        for (int j = 0; j < 4; j++) {
            int r0  = rowBase + wm * 32 + i * 16 + gg;
            int col = colBase + wn * 32 + j * 8 + 2 * t4;
            float2 b2 = *(const float2*)&bias[col];
#pragma unroll
            for (int h = 0; h < 2; h++) {
                int m = r0 + h * 8;
                float x = c[i][j][h * 2 + 0] + b2.x;
                float y = c[i][j][h * 2 + 1] + b2.y;
                if (mode == 0) {
                    *(float2*)&outPlain[(size_t)m * D_ + col] = make_float2(x, y);
                } else {
                    int bb = m >> 11, ss = m & (S_ - 1);
                    int hh = col >> 6, hd = col & 63;
                    __half* tgt = (mode == 1) ? g_q : g_k;
                    *(uint32_t*)&tgt[(((size_t)(bb * H_ + hh)) * S_ + ss) * HD_ + hd] =
                        f2h2(x, y);
                }
            }
        }
    }
}

// ============================================================
// Fused causal attention, warp tile 16x64 (8 warps = 128 rows).
// E (PV A-operand) comes DIRECTLY from S accumulators (fragment
// layout identity); rowsums/inv live entirely in registers.
// Paired q-tiles, triple-buffered K / K+V, single-sync pipeline.
// Smem: E32 f32[128][68] (Q staging aliases) | K 3x[64][72] | V 3x[64][72]
// ============================================================
static constexpr int SQ_  = 68;
static constexpr int SH_  = 72;
static constexpr int OFF_K   = 128 * SQ_ * 4;            // 34816
static constexpr int OFF_V   = OFF_K + 3 * 64 * SH_ * 2; // 62464
static constexpr int ATTN_SMEM = OFF_V + 3 * 64 * SH_ * 2; // 90112 B

__global__ __launch_bounds__(256, 2) void attn_kernel(float* __restrict__ P, int writeP)
{
    extern __shared__ char smc[];
    float*  E32   = (float*)smc;
    __half* Qh    = (__half*)smc;            // aliases E32 during Q staging
    __half* Kdb   = (__half*)(smc + OFF_K);
    __half* Vdb   = (__half*)(smc + OFF_V);

    const int tid  = threadIdx.x;
    const int lane = tid & 31;
    const int w    = tid >> 5;    // warp owns rows [w*16, w*16+16)
    const int gg   = lane >> 2;
    const int t4   = lane & 3;
    const int bh   = blockIdx.y;

    const __half* Qg = g_q + (size_t)bh * S_ * HD_;
    const __half* Kg = g_k + (size_t)bh * S_ * HD_;
    const __half* Vg = g_v + (size_t)bh * S_ * HD_;   // [hd][s]

    const uint32_t sQ = smem_u32(Qh);
    const uint32_t sK = smem_u32(Kdb);
    const uint32_t sV = smem_u32(Vdb);

    auto stageK = [&](int b, int k0) {
#pragma unroll
        for (int i = 0; i < 2; i++) {
            int idx = tid + i * 256;
            int row = idx >> 3, c = (idx & 7) * 8;
            cp_async16(sK + (uint32_t)(b * 64 * SH_ + row * SH_ + c) * 2u,
                       &Kg[(size_t)(k0 + row) * HD_ + c]);
        }
    };
    auto stageV = [&](int b, int k0) {
#pragma unroll
        for (int i = 0; i < 2; i++) {
            int idx = tid + i * 256;
            int row = idx >> 3, c = (idx & 7) * 8;
            cp_async16(sV + (uint32_t)(b * 64 * SH_ + row * SH_ + c) * 2u,
                       &Vg[(size_t)row * S_ + k0 + c]);
        }
    };

#pragma unroll 1
    for (int p = 0; p < 2; p++) {
        const int qt = p == 0 ? (NQT2_ - 1) - (int)blockIdx.x : (int)blockIdx.x;
        const int q0 = qt * QT_;
        __syncthreads();  // previous pair fully done

        // stage Q tile (fp16, pre-scaled)
#pragma unroll
        for (int i = 0; i < 4; i++) {
            int idx = tid + i * 256;
            int row = idx >> 3, c = (idx & 7) * 8;
            cp_async16(sQ + (uint32_t)(row * SH_ + c) * 2u,
                       &Qg[(size_t)(q0 + row) * HD_ + c]);
        }
        asm volatile("cp.async.commit_group;" ::: "memory");
        asm volatile("cp.async.wait_group 0;" ::: "memory");
        __syncthreads();

        // Q fragments -> registers (rows w*16..+16)
        uint32_t qf[4][4];
#pragma unroll
        for (int ck = 0; ck < 4; ck++)
            ldsm4(lm_addr(sQ, lane, w * 16, ck * 16, SH_),
                  qf[ck][0], qf[ck][1], qf[ck][2], qf[ck][3]);
        __syncthreads();  // Q region now free (E32 aliases it)

        const int nkt = 2 * qt + 2;

        // ================= sweep 1: rowsums =================
        stageK(0, 0);
        asm volatile("cp.async.commit_group;" ::: "memory");
        stageK(1, 64);
        asm volatile("cp.async.commit_group;" ::: "memory");

        float rs0 = 0.f, rs1 = 0.f;
        for (int kt = 0; kt < nkt; kt++) {
            if (kt + 1 < nkt) asm volatile("cp.async.wait_group 1;" ::: "memory");
            else              asm volatile("cp.async.wait_group 0;" ::: "memory");
            __syncthreads();
            if (kt + 2 < nkt) {
                stageK((kt + 2) % 3, (kt + 2) * 64);
                asm volatile("cp.async.commit_group;" ::: "memory");
            }

            const uint32_t kB = sK + (uint32_t)((kt % 3) * 64 * SH_) * 2u;
            float s[8][4];
#pragma unroll
            for (int j = 0; j < 8; j++)
#pragma unroll
                for (int q = 0; q < 4; q++) s[j][q] = 0.f;
#pragma unroll
            for (int ck = 0; ck < 4; ck++) {
                uint32_t bf[8][2];
#pragma unroll
                for (int jp = 0; jp < 4; jp++)
                    ldsm4(lm_addr(kB, lane, jp * 16, ck * 16, SH_),
                          bf[jp * 2][0], bf[jp * 2 + 1][0],
                          bf[jp * 2][1], bf[jp * 2 + 1][1]);
#pragma unroll
                for (int j = 0; j < 8; j++)
                    mma16(s[j], qf[ck][0], qf[ck][1], qf[ck][2], qf[ck][3],
                          bf[j][0], bf[j][1]);
            }

            const int k0 = kt * 64;
            if (k0 + 63 <= q0 + w * 16) {
#pragma unroll
                for (int j = 0; j < 8; j++) {
                    rs0 += __expf(s[j][0]) + __expf(s[j][1]);
                    rs1 += __expf(s[j][2]) + __expf(s[j][3]);
                }
            } else {
                int qiA = q0 + w * 16 + gg, qiB = qiA + 8;
#pragma unroll
                for (int j = 0; j < 8; j++) {
                    int ki0 = k0 + j * 8 + 2 * t4, ki1 = ki0 + 1;
                    rs0 += ((ki0 <= qiA) ? __expf(s[j][0]) : 0.f)
                         + ((ki1 <= qiA) ? __expf(s[j][1]) : 0.f);
                    rs1 += ((ki0 <= qiB) ? __expf(s[j][2]) : 0.f)
                         + ((ki1 <= qiB) ? __expf(s[j][3]) : 0.f);
                }
            }
        }
        // quad reduce over t4 -> every lane has full row sums; inv in regs
        rs0 += __shfl_xor_sync(0xFFFFFFFF, rs0, 1);
        rs0 += __shfl_xor_sync(0xFFFFFFFF, rs0, 2);
        rs1 += __shfl_xor_sync(0xFFFFFFFF, rs1, 1);
        rs1 += __shfl_xor_sync(0xFFFFFFFF, rs1, 2);
        const float invA = 1.f / rs0;
        const float invB = 1.f / rs1;
        __syncthreads();  // all warps done with sweep-1 K buffers

        // ================= sweep 2: P + O =================
        float o[8][4];
#pragma unroll
        for (int j = 0; j < 8; j++)
#pragma unroll
            for (int q = 0; q < 4; q++) o[j][q] = 0.f;

        stageK(0, 0); stageV(0, 0);
        asm volatile("cp.async.commit_group;" ::: "memory");
        stageK(1, 64); stageV(1, 64);
        asm volatile("cp.async.commit_group;" ::: "memory");

        for (int kt = 0; kt < S_ / 64; kt++) {
            const int k0 = kt * 64;
            if (kt < nkt) {
                if (kt + 1 < nkt) asm volatile("cp.async.wait_group 1;" ::: "memory");
                else              asm volatile("cp.async.wait_group 0;" ::: "memory");
                __syncthreads();
                if (kt + 2 < nkt) {
                    stageK((kt + 2) % 3, (kt + 2) * 64);
                    stageV((kt + 2) % 3, (kt + 2) * 64);
                    asm volatile("cp.async.commit_group;" ::: "memory");
                }

                const uint32_t kB = sK + (uint32_t)((kt % 3) * 64 * SH_) * 2u;
                const uint32_t vB = sV + (uint32_t)((kt % 3) * 64 * SH_) * 2u;

                float s[8][4];
#pragma unroll
                for (int j = 0; j < 8; j++)
#pragma unroll
                    for (int q = 0; q < 4; q++) s[j][q] = 0.f;
#pragma unroll
                for (int ck = 0; ck < 4; ck++) {
                    uint32_t bf[8][2];
#pragma unroll
                    for (int jp = 0; jp < 4; jp++)
                        ldsm4(lm_addr(kB, lane, jp * 16, ck * 16, SH_),
                              bf[jp * 2][0], bf[jp * 2 + 1][0],
                              bf[jp * 2][1], bf[jp * 2 + 1][1]);
#pragma unroll
                    for (int j = 0; j < 8; j++)
                        mma16(s[j], qf[ck][0], qf[ck][1], qf[ck][2], qf[ck][3],
                              bf[j][0], bf[j][1]);
                }

                // e_norm = exp * inv, masked only on edge tiles
                if (k0 + 63 <= q0 + w * 16) {
#pragma unroll
                    for (int j = 0; j < 8; j++) {
                        s[j][0] = __expf(s[j][0]) * invA;
                        s[j][1] = __expf(s[j][1]) * invA;
                        s[j][2] = __expf(s[j][2]) * invB;
                        s[j][3] = __expf(s[j][3]) * invB;
                    }
                } else {
                    int qiA = q0 + w * 16 + gg, qiB = qiA + 8;
#pragma unroll
                    for (int j = 0; j < 8; j++) {
                        int ki0 = k0 + j * 8 + 2 * t4, ki1 = ki0 + 1;
                        s[j][0] = (ki0 <= qiA) ? __expf(s[j][0]) * invA : 0.f;
                        s[j][1] = (ki1 <= qiA) ? __expf(s[j][1]) * invA : 0.f;
                        s[j][2] = (ki0 <= qiB) ? __expf(s[j][2]) * invB : 0.f;
                        s[j][3] = (ki1 <= qiB) ? __expf(s[j][3]) * invB : 0.f;
                    }
                }

                // stage E (fp32) for coalesced P write
                if (writeP) {
                    int r0 = w * 16 + gg;
#pragma unroll
                    for (int j = 0; j < 8; j++) {
                        int cl = j * 8 + 2 * t4;
                        *(float2*)&E32[r0 * SQ_ + cl]       = make_float2(s[j][0], s[j][1]);
                        *(float2*)&E32[(r0 + 8) * SQ_ + cl] = make_float2(s[j][2], s[j][3]);
                    }
                    __syncthreads();
                    float* Pd = P + (size_t)bh * S_ * S_ + (size_t)q0 * S_ + k0;
#pragma unroll
                    for (int i = 0; i < 8; i++) {
                        int idx = tid + i * 256;
                        int row = idx >> 4, cc = (idx & 15) * 4;
                        float4 v = *(const float4*)&E32[row * SQ_ + cc];
                        stg_cs_v4(&Pd[(size_t)row * S_ + cc], v);
                    }
                }

                // O += E_norm @ V ; A-frags DIRECTLY from accumulators
#pragma unroll
                for (int ck = 0; ck < 4; ck++) {
                    uint32_t a0 = f2h2(s[2 * ck][0],     s[2 * ck][1]);
                    uint32_t a1 = f2h2(s[2 * ck][2],     s[2 * ck][3]);
                    uint32_t a2 = f2h2(s[2 * ck + 1][0], s[2 * ck + 1][1]);
                    uint32_t a3 = f2h2(s[2 * ck + 1][2], s[2 * ck + 1][3]);
                    uint32_t bf[8][2];
#pragma unroll
                    for (int jp = 0; jp < 4; jp++)
                        ldsm4(lm_addr(vB, lane, jp * 16, ck * 16, SH_),
                              bf[jp * 2][0], bf[jp * 2 + 1][0],
                              bf[jp * 2][1], bf[jp * 2 + 1][1]);
#pragma unroll
                    for (int j = 0; j < 8; j++)
                        mma16(o[j], a0, a1, a2, a3, bf[j][0], bf[j][1]);
                }
            } else if (writeP) {
                float* Pd = P + (size_t)bh * S_ * S_ + (size_t)q0 * S_ + k0;
                const float4 z = make_float4(0.f, 0.f, 0.f, 0.f);
#pragma unroll
                for (int i = 0; i < 8; i++) {
                    int idx = tid + i * 256;
                    int row = idx >> 4, cc = (idx & 15) * 4;
                    stg_cs_v4(&Pd[(size_t)row * S_ + cc], z);
                }
            }
        }

        // epilogue: O -> g_ao (fp16)
        const int bb = bh >> 4, hh = bh & 15;
        {
            int mA = bb * S_ + q0 + w * 16 + gg;
#pragma unroll
            for (int j = 0; j < 8; j++) {
                int cl = hh * 64 + j * 8 + 2 * t4;
                *(uint32_t*)&g_ao[(size_t)mA * D_ + cl]       = f2h2(o[j][0], o[j][1]);
                *(uint32_t*)&g_ao[(size_t)(mA + 8) * D_ + cl] = f2h2(o[j][2], o[j][3]);
            }
        }
    }
}

// ============================================================
extern "C" void kernel_launch(void* const* d_in, const int* in_sizes, int n_in,
                              void* d_out, int out_size)
{
    const float* query = (const float*)d_in[0];
    const float* key_  = (const float*)d_in[1];
    const float* value = (const float*)d_in[2];
    // d_in[3] = causal mask — handled analytically
    const float* Wq = (const float*)d_in[4];
    const float* bq = (const float*)d_in[5];
    const float* Wk = (const float*)d_in[6];
    const float* bk = (const float*)d_in[7];
    const float* Wv = (const float*)d_in[8];
    const float* bv = (const float*)d_in[9];
    const float* Wo = (const float*)d_in[10];
    const float* bo = (const float*)d_in[11];
    float* out = (float*)d_out;

    const long long outN  = (long long)M_ * D_;
    const long long attnN = (long long)BH_ * S_ * S_;

    int hasOut = 1, hasAttn = 0;
    float* Pdst = nullptr;
    if ((long long)out_size >= outN + attnN) { hasAttn = 1; Pdst = out + outN; }
    else if ((long long)out_size == attnN)   { hasOut = 0; hasAttn = 1; Pdst = out; }

    cudaFuncSetAttribute(attn_kernel,
                         cudaFuncAttributeMaxDynamicSharedMemorySize, ATTN_SMEM);
    cudaFuncSetAttribute(gemm_tc_kernel,
                         cudaFuncAttributeMaxDynamicSharedMemorySize, GEMM_SMEM);

    convert_kernel<<<512, 256>>>(
        (const float4*)query, (const float4*)key_, (const float4*)value,
        (const float4*)Wq, (const float4*)Wk, (const float4*)Wv,
        (const float4*)Wo, (const float4*)bq);

    // fused Q/K/V projections: 16 x 32 x 3 = 1536 CTAs
    gemm_tc_kernel<<<dim3(D_ / 64, M_ / 128, 3), 256, GEMM_SMEM>>>(
        bk, bv, nullptr, nullptr, 99);

    // attention: paired q-tiles, uniform work, single wave (256 CTAs)
    attn_kernel<<<dim3(NQT2_ / 2, BH_), 256, ATTN_SMEM>>>(Pdst, hasAttn);

    if (hasOut)
        gemm_tc_kernel<<<dim3(D_ / 64, M_ / 128, 1), 256, GEMM_SMEM>>>(
            nullptr, nullptr, bo, out, 0);
}